// round 12
// baseline (speedup 1.0000x reference)
#include <cuda_runtime.h>
#include <cuda_bf16.h>
#include <cstddef>
#include <cstdint>

#define DIMN   512
#define NSLOT  32
#define BATCH  32
#define TSTEPS 2048
#define RANKS  8      // cluster size = d-chunks
#define BPC    2      // batches per CTA
#define DCH    64     // d columns per CTA
#define NTHR   512

// ---------------- scratch ----------------
__device__ float g_pre[(size_t)BATCH * TSTEPS * DIMN];
__device__ float g_WhP[DIMN * DIMN];   // packed: float4 idx = k4*DIMN + d
__device__ float g_WwP[DIMN * DIMN];

// ---------------- PTX helpers ----------------
__device__ __forceinline__ uint32_t smem_u32(const void* p) {
    uint32_t a;
    asm("{ .reg .u64 t; cvta.to.shared.u64 t, %1; cvt.u32.u64 %0, t; }"
        : "=r"(a) : "l"(p));
    return a;
}
__device__ __forceinline__ uint32_t mapa_rank(uint32_t laddr, uint32_t rank) {
    uint32_t r;
    asm("mapa.shared::cluster.u32 %0, %1, %2;" : "=r"(r) : "r"(laddr), "r"(rank));
    return r;
}
__device__ __forceinline__ void sts_cluster_f32(uint32_t addr, float v) {
    asm volatile("st.shared::cluster.f32 [%0], %1;" :: "r"(addr), "f"(v) : "memory");
}
__device__ __forceinline__ void sts_cluster_f32x2(uint32_t addr, float a, float b) {
    asm volatile("st.shared::cluster.v2.f32 [%0], {%1, %2};"
                 :: "r"(addr), "f"(a), "f"(b) : "memory");
}
__device__ __forceinline__ void mbar_init(uint32_t addr, uint32_t cnt) {
    asm volatile("mbarrier.init.shared.b64 [%0], %1;" :: "r"(addr), "r"(cnt) : "memory");
}
__device__ __forceinline__ void mbar_arrive_cl(uint32_t remAddr) {
    asm volatile("mbarrier.arrive.release.cluster.shared::cluster.b64 _, [%0];"
                 :: "r"(remAddr) : "memory");
}
__device__ __forceinline__ void mbar_wait_parity_cl(uint32_t addr, uint32_t parity) {
    asm volatile(
        "{\n\t"
        ".reg .pred P;\n\t"
        "LAB_WAIT_%=:\n\t"
        "mbarrier.try_wait.parity.acquire.cluster.shared::cta.b64 P, [%0], %1, 0x989680;\n\t"
        "@P bra.uni LAB_DONE_%=;\n\t"
        "bra.uni LAB_WAIT_%=;\n\t"
        "LAB_DONE_%=:\n\t"
        "}"
        :: "r"(addr), "r"(parity) : "memory");
}
__device__ __forceinline__ void cluster_sync_() {
    asm volatile("barrier.cluster.arrive.aligned;\n\tbarrier.cluster.wait.aligned;" ::: "memory");
}

__global__ void dummy_k() {}

// ---------------- weight packing ----------------
__global__ void pack_weights(const float* __restrict__ Wh,
                             const float* __restrict__ Ww) {
    int idx = blockIdx.x * blockDim.x + threadIdx.x;
    if (idx >= DIMN * DIMN) return;
    int d = idx / DIMN;
    int k = idx % DIMN;
    int dst = ((k >> 2) * DIMN + d) * 4 + (k & 3);
    g_WhP[dst] = Wh[idx];
    g_WwP[dst] = Ww[idx];
}

// ---------------- pre-GEMM ----------------
__global__ __launch_bounds__(256) void gemm_pre(
    const float* __restrict__ X,
    const float* __restrict__ W,
    const float* __restrict__ bias)
{
    __shared__ float As[8][128];
    __shared__ float Bs[8][64];
    const int tid = threadIdx.x;
    const int m0 = blockIdx.y * 128;
    const int n0 = blockIdx.x * 64;
    const int trow = tid >> 4;
    const int tcol = tid & 15;
    float acc[8][4];
#pragma unroll
    for (int i = 0; i < 8; ++i)
#pragma unroll
        for (int j = 0; j < 4; ++j) acc[i][j] = 0.f;
    const int a_m  = tid >> 1;
    const int a_k4 = (tid & 1) * 4;
    for (int k0 = 0; k0 < DIMN; k0 += 8) {
        float4 av = *reinterpret_cast<const float4*>(
            X + (size_t)(m0 + a_m) * DIMN + k0 + a_k4);
        As[a_k4 + 0][a_m] = av.x;
        As[a_k4 + 1][a_m] = av.y;
        As[a_k4 + 2][a_m] = av.z;
        As[a_k4 + 3][a_m] = av.w;
        if (tid < 128) {
            int bn  = tid >> 1;
            int bk4 = (tid & 1) * 4;
            float4 bv = *reinterpret_cast<const float4*>(
                W + (size_t)(n0 + bn) * DIMN + k0 + bk4);
            Bs[bk4 + 0][bn] = bv.x;
            Bs[bk4 + 1][bn] = bv.y;
            Bs[bk4 + 2][bn] = bv.z;
            Bs[bk4 + 3][bn] = bv.w;
        }
        __syncthreads();
#pragma unroll
        for (int kk = 0; kk < 8; ++kk) {
            float4 ra0 = *reinterpret_cast<const float4*>(&As[kk][trow * 8]);
            float4 ra1 = *reinterpret_cast<const float4*>(&As[kk][trow * 8 + 4]);
            float4 rb  = *reinterpret_cast<const float4*>(&Bs[kk][tcol * 4]);
            float ra[8] = {ra0.x, ra0.y, ra0.z, ra0.w, ra1.x, ra1.y, ra1.z, ra1.w};
            float rbv[4] = {rb.x, rb.y, rb.z, rb.w};
#pragma unroll
            for (int i = 0; i < 8; ++i)
#pragma unroll
                for (int j = 0; j < 4; ++j) acc[i][j] += ra[i] * rbv[j];
        }
        __syncthreads();
    }
    float4 bj = *reinterpret_cast<const float4*>(bias + n0 + tcol * 4);
#pragma unroll
    for (int i = 0; i < 8; ++i) {
        float4 v;
        v.x = acc[i][0] + bj.x;
        v.y = acc[i][1] + bj.y;
        v.z = acc[i][2] + bj.z;
        v.w = acc[i][3] + bj.w;
        *reinterpret_cast<float4*>(
            &g_pre[(size_t)(m0 + trow * 8 + i) * DIMN + n0 + tcol * 4]) = v;
    }
}

// ---------------- exact entmax-1.5 ----------------
__device__ __forceinline__ float entmax_coef(float raw, float* __restrict__ sb, int lane) {
    const unsigned FULL = 0xffffffffu;
    float z = raw * 0.5f;
    float m = z;
#pragma unroll
    for (int o = 16; o > 0; o >>= 1) m = fmaxf(m, __shfl_xor_sync(FULL, m, o));
    z -= m;
    int rank = 0;
#pragma unroll
    for (int j = 0; j < 32; ++j) {
        float zj = __shfl_sync(FULL, z, j);
        rank += (zj > z) || (zj == z && j < lane);
    }
    sb[rank] = z;
    __syncwarp();
    float zs = sb[lane];
    float cs = zs, cq = zs * zs;
#pragma unroll
    for (int o = 1; o < 32; o <<= 1) {
        float a  = __shfl_up_sync(FULL, cs, o);
        float bq = __shfl_up_sync(FULL, cq, o);
        if (lane >= o) { cs += a; cq += bq; }
    }
    float k    = (float)(lane + 1);
    float mean = cs / k;
    float msq  = cq / k;
    float ss   = k * (msq - mean * mean);
    float delta = fmaxf((1.f - ss) / k, 0.f);
    float tau   = mean - sqrtf(delta);
    unsigned sup = __ballot_sync(FULL, tau <= zs);
    int kstar = __popc(sup) - 1;
    float tau_star = __shfl_sync(FULL, tau, kstar);
    float p = fmaxf(z - tau_star, 0.f);
    return p * p;
}

// ---------------- SMEM float offsets ----------------
#define SM_WSM    0       // W_h slice [128 k4][64 dl] f4   32768
#define SM_PARTH  32768   // [8 seg][2 b][64]                1024
#define SM_PARTW  33792   // [8 seg][2 b][64]                1024
#define SM_XW     34816   // [2 par][2 b][512]               2048
#define SM_WVEC   36864   // [2][64]                         128
#define SM_COEFA  36992   // [2][32]                         64
#define SM_COEFB  37056   // [2][32]                         64
#define SM_SORT   37120   // [2][32]                         64
#define SM_TAPE   37184   // [2][32][65]                     4160
#define SM_XC     41344   // [2 par][8 rk][2 b][66]          2112
#define SM_MBARB  43456   // u64
#define SM_MBARC  43458   // u64
#define SM_FLOATS 43460

// ---------------- persistent recurrence: BPC=2, Wh in smem, Ww streamed ------
__global__ void __launch_bounds__(NTHR, 1) __cluster_dims__(RANKS, 1, 1)
recur12(const float* __restrict__ tape0,
        const float* __restrict__ work0,
        float* __restrict__ out_hseq,
        float* __restrict__ out_tape,
        float* __restrict__ out_hlast)
{
    extern __shared__ float sm[];
    float* wsm    = sm + SM_WSM;
    float* part_h = sm + SM_PARTH;
    float* part_w = sm + SM_PARTW;
    float* xw     = sm + SM_XW;
    float* wvec   = sm + SM_WVEC;
    float* coefA  = sm + SM_COEFA;
    float* coefB  = sm + SM_COEFB;
    float* sortb  = sm + SM_SORT;
    float* tape   = sm + SM_TAPE;
    float* xc     = sm + SM_XC;

    const int tid  = threadIdx.x;
    const int lane = tid & 31;
    const int wid  = tid >> 5;
    const int rk   = blockIdx.x & (RANKS - 1);
    const int bg   = blockIdx.x >> 3;
    const int b0   = bg * BPC;
    const int dbase = rk * DCH;
    const float invsd = 0.044194173824159216f;  // 1/sqrt(512)

    const uint32_t sbase = smem_u32(sm);
    const uint32_t a_xw  = sbase + SM_XW * 4u;
    const uint32_t a_xc  = sbase + SM_XC * 4u;
    const uint32_t a_mbB = sbase + SM_MBARB * 4u;
    const uint32_t a_mbC = sbase + SM_MBARC * 4u;

    if (tid == 0) {
        mbar_init(a_mbB, RANKS);
        mbar_init(a_mbC, RANKS);
    }

    // ---- prologue: tape slice, work0, W_h slice -> smem ----
    for (int i = tid; i < BPC * NSLOT * DCH; i += NTHR) {          // 4096
        int b = i >> 11;
        int n = (i >> 6) & 31;
        int d = i & 63;
        tape[(b * NSLOT + n) * 65 + d] =
            tape0[((size_t)(b0 + b) * NSLOT + n) * DIMN + dbase + d];
    }
    for (int i = tid; i < BPC * DIMN; i += NTHR) {                 // 1024
        int b = i >> 9;
        int k = i & 511;
        xw[b * DIMN + k] = work0[(size_t)(b0 + b) * DIMN + k];
    }
    {
        float4* wsm4 = reinterpret_cast<float4*>(wsm);
        const float4* src = reinterpret_cast<const float4*>(g_WhP);
        for (int i = tid; i < 8192; i += NTHR)
            wsm4[i] = src[(size_t)(i >> 6) * DIMN + dbase + (i & 63)];
    }
    __syncthreads();
    cluster_sync_();

    // ---- initial read-scores exchange (parity 0) ----
    if (wid < BPC) {
        const int b = wid;
        const float* tr = tape + (b * NSLOT + lane) * 65;
        const float* wk = xw + b * DIMN + dbase;
        float s = 0.f;
#pragma unroll
        for (int d = 0; d < DCH; ++d) s += tr[d] * wk[d];
        uint32_t off = a_xc + (unsigned)(rk * 132 + b * 66 + 2 * lane) * 4u;
#pragma unroll
        for (int p = 0; p < RANKS; ++p) sts_cluster_f32(mapa_rank(off, p), s);
    }
    __syncthreads();
    if (tid == 0) {
#pragma unroll
        for (int p = 0; p < RANKS; ++p) mbar_arrive_cl(mapa_rank(a_mbC, p));
    }
    mbar_wait_parity_cl(a_mbC, 0u);
    if (wid < BPC) {
        const int b = wid;
        float s = 0.f;
#pragma unroll
        for (int r = 0; r < RANKS; ++r) s += xc[r * 132 + b * 66 + 2 * lane];
        coefA[b * 32 + lane] = entmax_coef(s * invsd, sortb + b * 32, lane);
    }

    // ---- prologue W_h GEMV on work0 (warps 0-7, from smem) ----
    if (wid < 8) {
        const float4* X4 = reinterpret_cast<const float4*>(xw);
        const float4* W4 = reinterpret_cast<const float4*>(wsm)
                           + (size_t)(wid * 16) * 64 + lane;
        float h00 = 0, h01 = 0, h10 = 0, h11 = 0;
#pragma unroll
        for (int i = 0; i < 16; ++i) {
            int k4 = wid * 16 + i;
            float4 w0 = W4[i * 64];
            float4 w1 = W4[i * 64 + 32];
            float4 x0 = X4[k4];
            float4 x1 = X4[128 + k4];
            h00 += w0.x*x0.x + w0.y*x0.y + w0.z*x0.z + w0.w*x0.w;
            h10 += w1.x*x0.x + w1.y*x0.y + w1.z*x0.z + w1.w*x0.w;
            h01 += w0.x*x1.x + w0.y*x1.y + w0.z*x1.z + w0.w*x1.w;
            h11 += w1.x*x1.x + w1.y*x1.y + w1.z*x1.z + w1.w*x1.w;
        }
        float* ph = part_h + wid * 128;
        ph[lane] = h00;  ph[lane + 32] = h10;
        ph[64 + lane] = h01;  ph[96 + lane] = h11;
    }

    // initial pre prefetch (t=0)
    float pre_reg = 0.f;
    if (tid < 128) {
        const int b = tid >> 6, d = tid & 63;
        pre_reg = __ldcs(&g_pre[((size_t)(b0 + b) * TSTEPS) * DIMN + dbase + d]);
    }
    __syncthreads();

    for (int t = 0; t < TSTEPS; ++t) {
        const int ni = (t & 1) ^ 1;
        const int cp = (t + 1) & 1;
        const int bp = t & 1;

        // ---- finish h(t): tid<128 (b=tid>>6, d=tid&63) ----
        if (tid < 128) {
            const int b = tid >> 6, d = tid & 63;
            float acc = pre_reg;
#pragma unroll
            for (int s = 0; s < 8; ++s) acc += part_h[s * 128 + b * 64 + d];
            const float* tr = tape + b * NSLOT * 65 + d;
            const float* cf = coefA + b * 32;
#pragma unroll 8
            for (int n = 0; n < NSLOT; ++n) acc += cf[n] * tr[n * 65];
            float h = tanhf(acc);
            __stcs(&out_hseq[((size_t)(b0 + b) * TSTEPS + t) * DIMN + dbase + d], h);
            uint32_t off = a_xw + (unsigned)(ni * 1024 + b * DIMN + dbase + d) * 4u;
#pragma unroll
            for (int p = 0; p < RANKS; ++p) sts_cluster_f32(mapa_rank(off, p), h);
            int tn = (t + 1 < TSTEPS) ? t + 1 : t;
            pre_reg = __ldcs(&g_pre[((size_t)(b0 + b) * TSTEPS + tn) * DIMN + dbase + d]);
        }
        __syncthreads();
        if (tid == 0) {
#pragma unroll
            for (int p = 0; p < RANKS; ++p) mbar_arrive_cl(mapa_rank(a_mbB, p));
        }
        mbar_wait_parity_cl(a_mbB, (uint32_t)bp);

        // ---- dual GEMV on h(t): warps 0-7 W_h (smem), warps 8-15 W_w (gmem) ----
        {
            const float4* X4 = reinterpret_cast<const float4*>(xw + ni * 1024);
            if (wid < 8) {
                const float4* W4 = reinterpret_cast<const float4*>(wsm)
                                   + (size_t)(wid * 16) * 64 + lane;
                float h00 = 0, h01 = 0, h10 = 0, h11 = 0;
#pragma unroll
                for (int i = 0; i < 16; ++i) {
                    int k4 = wid * 16 + i;
                    float4 w0 = W4[i * 64];
                    float4 w1 = W4[i * 64 + 32];
                    float4 x0 = X4[k4];
                    float4 x1 = X4[128 + k4];
                    h00 += w0.x*x0.x + w0.y*x0.y + w0.z*x0.z + w0.w*x0.w;
                    h10 += w1.x*x0.x + w1.y*x0.y + w1.z*x0.z + w1.w*x0.w;
                    h01 += w0.x*x1.x + w0.y*x1.y + w0.z*x1.z + w0.w*x1.w;
                    h11 += w1.x*x1.x + w1.y*x1.y + w1.z*x1.z + w1.w*x1.w;
                }
                float* ph = part_h + wid * 128;
                ph[lane] = h00;  ph[lane + 32] = h10;
                ph[64 + lane] = h01;  ph[96 + lane] = h11;
            } else {
                const int w = wid - 8;
                const float4* W4 = reinterpret_cast<const float4*>(g_WwP)
                                   + (size_t)(w * 16) * DIMN + dbase + lane;
                float w00 = 0, w01 = 0, w10 = 0, w11 = 0;
#pragma unroll
                for (int i = 0; i < 16; ++i) {
                    int k4 = w * 16 + i;
                    float4 c0 = __ldg(W4 + (size_t)i * DIMN);
                    float4 c1 = __ldg(W4 + (size_t)i * DIMN + 32);
                    float4 x0 = X4[k4];
                    float4 x1 = X4[128 + k4];
                    w00 += c0.x*x0.x + c0.y*x0.y + c0.z*x0.z + c0.w*x0.w;
                    w10 += c1.x*x0.x + c1.y*x0.y + c1.z*x0.z + c1.w*x0.w;
                    w01 += c0.x*x1.x + c0.y*x1.y + c0.z*x1.z + c0.w*x1.w;
                    w11 += c1.x*x1.x + c1.y*x1.y + c1.z*x1.z + c1.w*x1.w;
                }
                float* pw = part_w + w * 128;
                pw[lane] = w00;  pw[lane + 32] = w10;
                pw[64 + lane] = w01;  pw[96 + lane] = w11;
            }
        }
        __syncthreads();

        // ---- reduce wvec (tid<128) ----
        if (tid < 128) {
            const int b = tid >> 6, d = tid & 63;
            float acc = 0.f;
#pragma unroll
            for (int s = 0; s < 8; ++s) acc += part_w[s * 128 + b * 64 + d];
            wvec[b * 64 + d] = acc;
        }
        __syncthreads();

        // ---- scores: warps 0-1 (sA,sB); warps 2-3 (sC) ----
        if (wid < BPC) {
            const int b = wid;
            const float* tr = tape + (b * NSLOT + lane) * 65;
            const float* wv = wvec + b * 64;
            const float* hh = xw + ni * 1024 + b * DIMN + dbase;
            float sA = 0.f, sB = 0.f;
#pragma unroll
            for (int d = 0; d < DCH; ++d) {
                float tv = tr[d];
                sA += tv * wv[d];
                sB += tv * hh[d];
            }
            uint32_t off = a_xc + (unsigned)(cp * 1056 + rk * 132 + b * 66 + 2 * lane) * 4u;
#pragma unroll
            for (int p = 0; p < RANKS; ++p) sts_cluster_f32x2(mapa_rank(off, p), sA, sB);
        } else if (wid < 4) {
            const int b = wid - 2;
            const float* hh = xw + ni * 1024 + b * DIMN + dbase;
            float v = wvec[b * 64 + lane] * hh[lane]
                    + wvec[b * 64 + 32 + lane] * hh[32 + lane];
#pragma unroll
            for (int o = 16; o > 0; o >>= 1) v += __shfl_xor_sync(0xffffffffu, v, o);
            if (lane == 0) {
                uint32_t off = a_xc + (unsigned)(cp * 1056 + rk * 132 + b * 66 + 64) * 4u;
#pragma unroll
                for (int p = 0; p < RANKS; ++p) sts_cluster_f32(mapa_rank(off, p), v);
            }
        }
        __syncthreads();
        if (tid == 0) {
#pragma unroll
            for (int p = 0; p < RANKS; ++p) mbar_arrive_cl(mapa_rank(a_mbC, p));
        }
        mbar_wait_parity_cl(a_mbC, (uint32_t)cp);

        // ---- D: reduce; beta = entmax(sA); alpha(t+1) via score recurrence ----
        if (wid < BPC) {
            const int b = wid;
            const float* base = xc + cp * 1056 + b * 66;
            float sA = 0.f, sB = 0.f, sC = 0.f;
#pragma unroll
            for (int r = 0; r < RANKS; ++r) {
                float2 pr = *reinterpret_cast<const float2*>(base + r * 132 + 2 * lane);
                sA += pr.x;
                sB += pr.y;
                sC += base[r * 132 + 64];
            }
            float beta = entmax_coef(sA * invsd, sortb + b * 32, lane);
            coefB[b * 32 + lane] = beta;
            float rnext = ((1.f - beta) * sB + beta * sC) * invsd;
            coefA[b * 32 + lane] = entmax_coef(rnext, sortb + b * 32, lane);
        }
        __syncthreads();

        // ---- tape convex update (16 warps: b = wid&1, 4-slot group) ----
        {
            const int b = wid & 1;
            const int n0 = (wid >> 1) * 4;
            const float* wv = wvec + b * 64;
            const float* cf = coefB + b * 32 + n0;
            float* tb = tape + (b * NSLOT + n0) * 65;
#pragma unroll
            for (int n = 0; n < 4; ++n) {
                float bt = cf[n], omb = 1.f - bt;
                float* row = tb + n * 65;
                row[lane]      = row[lane]      * omb + bt * wv[lane];
                row[lane + 32] = row[lane + 32] * omb + bt * wv[lane + 32];
            }
        }
        __syncthreads();
    }

    // ---- final outputs ----
    for (int i = tid; i < BPC * NSLOT * DCH; i += NTHR) {
        int b = i >> 11;
        int n = (i >> 6) & 31;
        int d = i & 63;
        out_tape[((size_t)(b0 + b) * NSLOT + n) * DIMN + dbase + d] =
            tape[(b * NSLOT + n) * 65 + d];
    }
    if (tid < 128) {
        const int b = tid >> 6, d = tid & 63;
        // h(2047): ni at t=2047 is 0
        out_hlast[(size_t)(b0 + b) * DIMN + dbase + d] = xw[b * DIMN + dbase + d];
    }
    cluster_sync_();
}

// ---------------- launch ----------------
extern "C" void kernel_launch(void* const* d_in, const int* in_sizes, int n_in,
                              void* d_out, int out_size) {
    const float* x     = (const float*)d_in[0];
    const float* tape0 = (const float*)d_in[1];
    const float* work0 = (const float*)d_in[2];
    const float* Wh    = (const float*)d_in[3];
    const float* Wx    = (const float*)d_in[4];
    const float* bh    = (const float*)d_in[5];
    const float* Ww    = (const float*)d_in[6];

    float* out       = (float*)d_out;
    float* out_hseq  = out;
    float* out_tape  = out + (size_t)BATCH * TSTEPS * DIMN;
    float* out_hlast = out_tape + (size_t)BATCH * NSLOT * DIMN;

    dummy_k<<<1, 32>>>();

    pack_weights<<<(DIMN * DIMN + 511) / 512, 512>>>(Wh, Ww);

    dim3 ggrid(DIMN / 64, (BATCH * TSTEPS) / 128);
    gemm_pre<<<ggrid, 256>>>(x, Wx, bh);

    const int smem_bytes = SM_FLOATS * 4 + 16;   // ~174 KB
    cudaFuncSetAttribute(recur12, cudaFuncAttributeMaxDynamicSharedMemorySize, smem_bytes);
    recur12<<<(BATCH / BPC) * RANKS, NTHR, smem_bytes>>>(
        tape0, work0, out_hseq, out_tape, out_hlast);
}

// round 13
// speedup vs baseline: 2.7242x; 2.7242x over previous
#include <cuda_runtime.h>
#include <cuda_bf16.h>
#include <cstddef>
#include <cstdint>

#define DIMN   512
#define NSLOT  32
#define BATCH  32
#define TSTEPS 2048
#define RANKS  8      // cluster size = d-chunks
#define BPC    4      // batches per CTA
#define DCH    64     // d columns per CTA
#define NTHR   512

// ---------------- scratch ----------------
__device__ float g_pre[(size_t)BATCH * TSTEPS * DIMN];
__device__ float g_WhP[DIMN * DIMN];   // packed: float4 idx = k4*DIMN + d
__device__ float g_WwP[DIMN * DIMN];

// ---------------- PTX helpers ----------------
__device__ __forceinline__ uint32_t smem_u32(const void* p) {
    uint32_t a;
    asm("{ .reg .u64 t; cvta.to.shared.u64 t, %1; cvt.u32.u64 %0, t; }"
        : "=r"(a) : "l"(p));
    return a;
}
__device__ __forceinline__ uint32_t mapa_rank(uint32_t laddr, uint32_t rank) {
    uint32_t r;
    asm("mapa.shared::cluster.u32 %0, %1, %2;" : "=r"(r) : "r"(laddr), "r"(rank));
    return r;
}
__device__ __forceinline__ void sts_cluster_f32(uint32_t addr, float v) {
    asm volatile("st.shared::cluster.f32 [%0], %1;" :: "r"(addr), "f"(v) : "memory");
}
__device__ __forceinline__ void sts_cluster_f32x2(uint32_t addr, float a, float b) {
    asm volatile("st.shared::cluster.v2.f32 [%0], {%1, %2};"
                 :: "r"(addr), "f"(a), "f"(b) : "memory");
}
__device__ __forceinline__ void mbar_init(uint32_t addr, uint32_t cnt) {
    asm volatile("mbarrier.init.shared.b64 [%0], %1;" :: "r"(addr), "r"(cnt) : "memory");
}
__device__ __forceinline__ void mbar_arrive_cl(uint32_t remAddr) {
    asm volatile("mbarrier.arrive.release.cluster.shared::cluster.b64 _, [%0];"
                 :: "r"(remAddr) : "memory");
}
__device__ __forceinline__ void mbar_wait_parity_cl(uint32_t addr, uint32_t parity) {
    asm volatile(
        "{\n\t"
        ".reg .pred P;\n\t"
        "LAB_WAIT_%=:\n\t"
        "mbarrier.try_wait.parity.acquire.cluster.shared::cta.b64 P, [%0], %1, 0x989680;\n\t"
        "@P bra.uni LAB_DONE_%=;\n\t"
        "bra.uni LAB_WAIT_%=;\n\t"
        "LAB_DONE_%=:\n\t"
        "}"
        :: "r"(addr), "r"(parity) : "memory");
}
__device__ __forceinline__ void cluster_sync_() {
    asm volatile("barrier.cluster.arrive.aligned;\n\tbarrier.cluster.wait.aligned;" ::: "memory");
}

__global__ void dummy_k() {}

// ---------------- weight packing ----------------
__global__ void pack_weights(const float* __restrict__ Wh,
                             const float* __restrict__ Ww) {
    int idx = blockIdx.x * blockDim.x + threadIdx.x;
    if (idx >= DIMN * DIMN) return;
    int d = idx / DIMN;
    int k = idx % DIMN;
    int dst = ((k >> 2) * DIMN + d) * 4 + (k & 3);
    g_WhP[dst] = Wh[idx];
    g_WwP[dst] = Ww[idx];
}

// ---------------- pre-GEMM ----------------
__global__ __launch_bounds__(256) void gemm_pre(
    const float* __restrict__ X,
    const float* __restrict__ W,
    const float* __restrict__ bias)
{
    __shared__ float As[8][128];
    __shared__ float Bs[8][64];
    const int tid = threadIdx.x;
    const int m0 = blockIdx.y * 128;
    const int n0 = blockIdx.x * 64;
    const int trow = tid >> 4;
    const int tcol = tid & 15;
    float acc[8][4];
#pragma unroll
    for (int i = 0; i < 8; ++i)
#pragma unroll
        for (int j = 0; j < 4; ++j) acc[i][j] = 0.f;
    const int a_m  = tid >> 1;
    const int a_k4 = (tid & 1) * 4;
    for (int k0 = 0; k0 < DIMN; k0 += 8) {
        float4 av = *reinterpret_cast<const float4*>(
            X + (size_t)(m0 + a_m) * DIMN + k0 + a_k4);
        As[a_k4 + 0][a_m] = av.x;
        As[a_k4 + 1][a_m] = av.y;
        As[a_k4 + 2][a_m] = av.z;
        As[a_k4 + 3][a_m] = av.w;
        if (tid < 128) {
            int bn  = tid >> 1;
            int bk4 = (tid & 1) * 4;
            float4 bv = *reinterpret_cast<const float4*>(
                W + (size_t)(n0 + bn) * DIMN + k0 + bk4);
            Bs[bk4 + 0][bn] = bv.x;
            Bs[bk4 + 1][bn] = bv.y;
            Bs[bk4 + 2][bn] = bv.z;
            Bs[bk4 + 3][bn] = bv.w;
        }
        __syncthreads();
#pragma unroll
        for (int kk = 0; kk < 8; ++kk) {
            float4 ra0 = *reinterpret_cast<const float4*>(&As[kk][trow * 8]);
            float4 ra1 = *reinterpret_cast<const float4*>(&As[kk][trow * 8 + 4]);
            float4 rb  = *reinterpret_cast<const float4*>(&Bs[kk][tcol * 4]);
            float ra[8] = {ra0.x, ra0.y, ra0.z, ra0.w, ra1.x, ra1.y, ra1.z, ra1.w};
            float rbv[4] = {rb.x, rb.y, rb.z, rb.w};
#pragma unroll
            for (int i = 0; i < 8; ++i)
#pragma unroll
                for (int j = 0; j < 4; ++j) acc[i][j] += ra[i] * rbv[j];
        }
        __syncthreads();
    }
    float4 bj = *reinterpret_cast<const float4*>(bias + n0 + tcol * 4);
#pragma unroll
    for (int i = 0; i < 8; ++i) {
        float4 v;
        v.x = acc[i][0] + bj.x;
        v.y = acc[i][1] + bj.y;
        v.z = acc[i][2] + bj.z;
        v.w = acc[i][3] + bj.w;
        *reinterpret_cast<float4*>(
            &g_pre[(size_t)(m0 + trow * 8 + i) * DIMN + n0 + tcol * 4]) = v;
    }
}

// ---------------- exact entmax-1.5 (warp-collective, lane = slot) ----------------
__device__ __forceinline__ float entmax_coef(float raw, float* __restrict__ sb, int lane) {
    const unsigned FULL = 0xffffffffu;
    float z = raw * 0.5f;
    float m = z;
#pragma unroll
    for (int o = 16; o > 0; o >>= 1) m = fmaxf(m, __shfl_xor_sync(FULL, m, o));
    z -= m;
    int rank = 0;
#pragma unroll
    for (int j = 0; j < 32; ++j) {
        float zj = __shfl_sync(FULL, z, j);
        rank += (zj > z) || (zj == z && j < lane);
    }
    sb[rank] = z;
    __syncwarp();
    float zs = sb[lane];
    float cs = zs, cq = zs * zs;
#pragma unroll
    for (int o = 1; o < 32; o <<= 1) {
        float a  = __shfl_up_sync(FULL, cs, o);
        float bq = __shfl_up_sync(FULL, cq, o);
        if (lane >= o) { cs += a; cq += bq; }
    }
    float k    = (float)(lane + 1);
    float mean = cs / k;
    float msq  = cq / k;
    float ss   = k * (msq - mean * mean);
    float delta = fmaxf((1.f - ss) / k, 0.f);
    float tau   = mean - sqrtf(delta);
    unsigned sup = __ballot_sync(FULL, tau <= zs);
    int kstar = __popc(sup) - 1;
    float tau_star = __shfl_sync(FULL, tau, kstar);
    float p = fmaxf(z - tau_star, 0.f);
    return p * p;
}

// ---------------- GEMV partials: 16 warps = 16 k-segments of 32 ----------------
__device__ __forceinline__ void gemv16(const float* __restrict__ Wp,
                                       const float4* __restrict__ xw4, // [4][128]
                                       float* __restrict__ part,
                                       int wid, int lane, int dbase) {
    const float4* W4 = reinterpret_cast<const float4*>(Wp)
                       + (size_t)(wid * 8) * DIMN + dbase + lane;
    float a0 = 0.f, a1 = 0.f, a2 = 0.f, a3 = 0.f;
    float b0 = 0.f, b1 = 0.f, b2 = 0.f, b3 = 0.f;
#pragma unroll
    for (int i = 0; i < 8; ++i) {
        float4 w0 = W4[(size_t)i * DIMN];
        float4 w1 = W4[(size_t)i * DIMN + 32];
        float4 k0 = xw4[0 * 128 + wid * 8 + i];
        float4 k1 = xw4[1 * 128 + wid * 8 + i];
        float4 k2 = xw4[2 * 128 + wid * 8 + i];
        float4 k3 = xw4[3 * 128 + wid * 8 + i];
        a0 += w0.x * k0.x + w0.y * k0.y + w0.z * k0.z + w0.w * k0.w;
        a1 += w0.x * k1.x + w0.y * k1.y + w0.z * k1.z + w0.w * k1.w;
        a2 += w0.x * k2.x + w0.y * k2.y + w0.z * k2.z + w0.w * k2.w;
        a3 += w0.x * k3.x + w0.y * k3.y + w0.z * k3.z + w0.w * k3.w;
        b0 += w1.x * k0.x + w1.y * k0.y + w1.z * k0.z + w1.w * k0.w;
        b1 += w1.x * k1.x + w1.y * k1.y + w1.z * k1.z + w1.w * k1.w;
        b2 += w1.x * k2.x + w1.y * k2.y + w1.z * k2.z + w1.w * k2.w;
        b3 += w1.x * k3.x + w1.y * k3.y + w1.z * k3.z + w1.w * k3.w;
    }
    float* pp = part + wid * 256 + lane;
    pp[0]   = a0;  pp[64]  = a1;  pp[128] = a2;  pp[192] = a3;
    pp[32]  = b0;  pp[96]  = b1;  pp[160] = b2;  pp[224] = b3;
}

// ---------------- SMEM float offsets (R5 layout, single part buffer) ----------
#define SM_PART   0       // [16][4][64]          4096
#define SM_XW     4096    // [2][4][512]          4096
#define SM_WVEC   8192    // [4][64]              256
#define SM_COEFA  8448    // [4][32]              128
#define SM_COEFB  8576    // [4][32]              128
#define SM_SORT   8704    // [4][32]              128
#define SM_TAPE   8832    // [4][32][65]          8320
#define SM_XC     17152   // [2][8][4][130]       8320
#define SM_MBARB  25472   // u64
#define SM_MBARC  25474   // u64
#define SM_FLOATS 25476

// ---------------- persistent recurrence (reordered pipeline) ----------------
__global__ void __launch_bounds__(NTHR, 1) __cluster_dims__(RANKS, 1, 1)
recur13(const float* __restrict__ tape0,
        const float* __restrict__ work0,
        float* __restrict__ out_hseq,
        float* __restrict__ out_tape,
        float* __restrict__ out_hlast)
{
    extern __shared__ float sm[];
    float* part  = sm + SM_PART;
    float* xw    = sm + SM_XW;
    float* wvec  = sm + SM_WVEC;
    float* coefA = sm + SM_COEFA;
    float* coefB = sm + SM_COEFB;
    float* sortb = sm + SM_SORT;
    float* tape  = sm + SM_TAPE;
    float* xc    = sm + SM_XC;

    const int tid  = threadIdx.x;
    const int lane = tid & 31;
    const int wid  = tid >> 5;
    const int rk   = blockIdx.x & (RANKS - 1);
    const int bg   = blockIdx.x >> 3;
    const int b0   = bg * BPC;
    const int dbase = rk * DCH;
    const float invsd = 0.044194173824159216f;  // 1/sqrt(512)

    const uint32_t sbase = smem_u32(sm);
    const uint32_t a_xw  = sbase + SM_XW * 4u;
    const uint32_t a_xc  = sbase + SM_XC * 4u;
    const uint32_t a_mbB = sbase + SM_MBARB * 4u;
    const uint32_t a_mbC = sbase + SM_MBARC * 4u;

    if (tid == 0) {
        mbar_init(a_mbB, RANKS);
        mbar_init(a_mbC, RANKS);
    }

    // ---- prologue loads ----
    for (int i = tid; i < BPC * NSLOT * DCH; i += NTHR) {
        int b = i >> 11;
        int n = (i >> 6) & 31;
        int d = i & 63;
        tape[(b * NSLOT + n) * 65 + d] =
            tape0[((size_t)(b0 + b) * NSLOT + n) * DIMN + dbase + d];
    }
    for (int i = tid; i < BPC * DIMN; i += NTHR) {
        int b = i >> 9;
        int k = i & 511;
        xw[b * DIMN + k] = work0[(size_t)(b0 + b) * DIMN + k];
    }
    __syncthreads();
    cluster_sync_();

    // ---- prologue: r_scores(0) exchange (C phase 0) -> coefA = alpha(0) ----
    if (wid < BPC) {
        const int b = wid;
        const float* tr = tape + (b * NSLOT + lane) * 65;
        const float* wk = xw + b * DIMN + dbase;
        float s = 0.f;
#pragma unroll
        for (int d = 0; d < DCH; ++d) s += tr[d] * wk[d];
        uint32_t off = a_xc + (unsigned)(rk * 520 + b * 130 + 2 * lane) * 4u;
#pragma unroll
        for (int p = 0; p < RANKS; ++p) sts_cluster_f32(mapa_rank(off, p), s);
    }
    __syncthreads();
    if (tid == 0) {
#pragma unroll
        for (int p = 0; p < RANKS; ++p) mbar_arrive_cl(mapa_rank(a_mbC, p));
    }
    mbar_wait_parity_cl(a_mbC, 0u);
    if (wid < BPC) {
        const int b = wid;
        const float* base = xc + b * 130 + 2 * lane;
        float s = 0.f;
#pragma unroll
        for (int r = 0; r < RANKS; ++r) s += base[r * 520] + base[r * 520 + 64];
        coefA[b * 32 + lane] = entmax_coef(s * invsd, sortb + b * 32, lane);
    }
    __syncthreads();

    // initial pre prefetch (t=0)
    float pre_reg = 0.f;
    if (tid < 256) {
        const int b = tid >> 6, d = tid & 63;
        pre_reg = __ldcs(&g_pre[((size_t)(b0 + b) * TSTEPS) * DIMN + dbase + d]);
    }

    for (int t = 0; t < TSTEPS; ++t) {
        const int oldi = t & 1;
        const int ni   = oldi ^ 1;

        // ---- A: W_h GEMV partials on h(t-1) (16 warps) — C exchange in flight ----
        gemv16(g_WhP, reinterpret_cast<const float4*>(xw + oldi * 2048),
               part, wid, lane, dbase);

        // ---- C-wait + deferred beta/alpha/tape from step t-1 ----
        if (t > 0) {
            mbar_wait_parity_cl(a_mbC, (uint32_t)(t & 1));
            float sBr = 0.f, sCr = 0.f, betar = 0.f;
            if (wid < BPC) {
                const int b = wid;
                const float* base = xc + (t & 1) * 4160 + b * 130;
                float sA = 0.f;
#pragma unroll
                for (int r = 0; r < RANKS; ++r) {
                    float2 p0 = *reinterpret_cast<const float2*>(base + r * 520 + 2 * lane);
                    float2 p1 = *reinterpret_cast<const float2*>(base + r * 520 + 64 + 2 * lane);
                    sA  += p0.x + p1.x;
                    sBr += p0.y + p1.y;
                    sCr += base[r * 520 + 128];
                }
                betar = entmax_coef(sA * invsd, sortb + b * 32, lane);
                coefB[b * 32 + lane] = betar;
            }
            __syncthreads();
            // alpha(t) (warps 0-3)  ||  tape update t-1 (warps 4-11)
            if (wid < BPC) {
                float rn = ((1.f - betar) * sBr + betar * sCr) * invsd;
                coefA[wid * 32 + lane] = entmax_coef(rn, sortb + wid * 32, lane);
            } else if (wid < 12) {
                const int idx = wid - 4;
                const int b  = idx >> 1;
                const int n0 = (idx & 1) * 16;
                const float* wv = wvec + b * 64;
                const float* cf = coefB + b * 32 + n0;
                float* tb = tape + (b * NSLOT + n0) * 65;
#pragma unroll
                for (int n = 0; n < 16; ++n) {
                    float bt = cf[n], omb = 1.f - bt;
                    float* row = tb + n * 65;
                    row[lane]      = row[lane]      * omb + bt * wv[lane];
                    row[lane + 32] = row[lane + 32] * omb + bt * wv[lane + 32];
                }
            }
        }
        __syncthreads();

        // ---- F: finish h(t) (tid<256); push h; prefetch pre(t+1) ----
        if (tid < 256) {
            const int b = tid >> 6, d = tid & 63;
            float acc = pre_reg;
#pragma unroll
            for (int s = 0; s < 16; ++s) acc += part[s * 256 + b * 64 + d];
            const float* tr = tape + b * NSLOT * 65 + d;
            const float* cf = coefA + b * 32;
#pragma unroll 8
            for (int n = 0; n < NSLOT; ++n) acc += cf[n] * tr[n * 65];
            float h = tanhf(acc);
            __stcs(&out_hseq[((size_t)(b0 + b) * TSTEPS + t) * DIMN + dbase + d], h);
            uint32_t off = a_xw + (unsigned)(ni * 2048 + b * DIMN + dbase + d) * 4u;
#pragma unroll
            for (int p = 0; p < RANKS; ++p) sts_cluster_f32(mapa_rank(off, p), h);
            int tn = (t + 1 < TSTEPS) ? t + 1 : t;
            pre_reg = __ldcs(&g_pre[((size_t)(b0 + b) * TSTEPS + tn) * DIMN + dbase + d]);
        }
        __syncthreads();
        if (tid == 0) {
#pragma unroll
            for (int p = 0; p < RANKS; ++p) mbar_arrive_cl(mapa_rank(a_mbB, p));
        }
        mbar_wait_parity_cl(a_mbB, (uint32_t)(t & 1));

        // ---- H: W_w GEMV partials on h(t) ----
        gemv16(g_WwP, reinterpret_cast<const float4*>(xw + ni * 2048),
               part, wid, lane, dbase);
        __syncthreads();

        // ---- I: reduce wvec ----
        if (tid < 256) {
            const int b = tid >> 6, d = tid & 63;
            float acc = 0.f;
#pragma unroll
            for (int s = 0; s < 16; ++s) acc += part[s * 256 + b * 64 + d];
            wvec[b * 64 + d] = acc;
        }
        __syncthreads();

        // ---- J: scores + push C (NO wait) ----
        {
            const int csl = (t + 1) & 1;
            if (wid < 8) {
                const int b = wid & 3, half = wid >> 2;
                const float* tr = tape + (b * NSLOT + lane) * 65 + half * 32;
                const float* wv = wvec + b * 64 + half * 32;
                const float* hh = xw + ni * 2048 + b * DIMN + dbase + half * 32;
                float sA = 0.f, sB = 0.f;
#pragma unroll
                for (int d = 0; d < 32; ++d) {
                    float tv = tr[d];
                    sA += tv * wv[d];
                    sB += tv * hh[d];
                }
                uint32_t off = a_xc + (unsigned)(csl * 4160 + rk * 520 + b * 130
                                                 + 2 * (half * 32 + lane)) * 4u;
#pragma unroll
                for (int p = 0; p < RANKS; ++p) sts_cluster_f32x2(mapa_rank(off, p), sA, sB);
            } else if (wid < 12) {
                const int b = wid - 8;
                const float* hh = xw + ni * 2048 + b * DIMN + dbase;
                float v = wvec[b * 64 + lane] * hh[lane]
                        + wvec[b * 64 + 32 + lane] * hh[32 + lane];
#pragma unroll
                for (int o = 16; o > 0; o >>= 1) v += __shfl_xor_sync(0xffffffffu, v, o);
                if (lane == 0) {
                    uint32_t off = a_xc + (unsigned)(csl * 4160 + rk * 520 + b * 130 + 128) * 4u;
#pragma unroll
                    for (int p = 0; p < RANKS; ++p) sts_cluster_f32(mapa_rank(off, p), v);
                }
            }
        }
        __syncthreads();
        if (tid == 0) {
#pragma unroll
            for (int p = 0; p < RANKS; ++p) mbar_arrive_cl(mapa_rank(a_mbC, p));
        }
        // no waitC here — consumed after GEMV_A of step t+1
    }

    // ---- epilogue: final beta(2047) + tape update ----
    mbar_wait_parity_cl(a_mbC, 0u);   // phase 2048, parity 0
    if (wid < BPC) {
        const int b = wid;
        const float* base = xc + 0 * 4160 + b * 130;   // slot (2047+1)&1 = 0
        float sA = 0.f;
#pragma unroll
        for (int r = 0; r < RANKS; ++r) {
            float2 p0 = *reinterpret_cast<const float2*>(base + r * 520 + 2 * lane);
            float2 p1 = *reinterpret_cast<const float2*>(base + r * 520 + 64 + 2 * lane);
            sA += p0.x + p1.x;
        }
        coefB[b * 32 + lane] = entmax_coef(sA * invsd, sortb + b * 32, lane);
    }
    __syncthreads();
    {
        const int b = wid & 3;
        const int n0 = (wid >> 2) * 8;
        const float* wv = wvec + b * 64;
        const float* cf = coefB + b * 32 + n0;
        float* tb = tape + (b * NSLOT + n0) * 65;
#pragma unroll
        for (int n = 0; n < 8; ++n) {
            float bt = cf[n], omb = 1.f - bt;
            float* row = tb + n * 65;
            row[lane]      = row[lane]      * omb + bt * wv[lane];
            row[lane + 32] = row[lane + 32] * omb + bt * wv[lane + 32];
        }
    }
    __syncthreads();

    // ---- final outputs ----
    for (int i = tid; i < BPC * NSLOT * DCH; i += NTHR) {
        int b = i >> 11;
        int n = (i >> 6) & 31;
        int d = i & 63;
        out_tape[((size_t)(b0 + b) * NSLOT + n) * DIMN + dbase + d] =
            tape[(b * NSLOT + n) * 65 + d];
    }
    if (tid < 256) {
        const int b = tid >> 6, d = tid & 63;
        // h(2047): ni at t=2047 is 0
        out_hlast[(size_t)(b0 + b) * DIMN + dbase + d] = xw[b * DIMN + dbase + d];
    }
    cluster_sync_();
}

// ---------------- launch ----------------
extern "C" void kernel_launch(void* const* d_in, const int* in_sizes, int n_in,
                              void* d_out, int out_size) {
    const float* x     = (const float*)d_in[0];
    const float* tape0 = (const float*)d_in[1];
    const float* work0 = (const float*)d_in[2];
    const float* Wh    = (const float*)d_in[3];
    const float* Wx    = (const float*)d_in[4];
    const float* bh    = (const float*)d_in[5];
    const float* Ww    = (const float*)d_in[6];

    float* out       = (float*)d_out;
    float* out_hseq  = out;
    float* out_tape  = out + (size_t)BATCH * TSTEPS * DIMN;
    float* out_hlast = out_tape + (size_t)BATCH * NSLOT * DIMN;

    dummy_k<<<1, 32>>>();

    pack_weights<<<(DIMN * DIMN + 511) / 512, 512>>>(Wh, Ww);

    dim3 ggrid(DIMN / 64, (BATCH * TSTEPS) / 128);
    gemm_pre<<<ggrid, 256>>>(x, Wx, bh);

    const int smem_bytes = SM_FLOATS * 4 + 16;
    cudaFuncSetAttribute(recur13, cudaFuncAttributeMaxDynamicSharedMemorySize, smem_bytes);
    recur13<<<(BATCH / BPC) * RANKS, NTHR, smem_bytes>>>(
        tape0, work0, out_hseq, out_tape, out_hlast);
}

// round 14
// speedup vs baseline: 2.7683x; 1.0162x over previous
#include <cuda_runtime.h>
#include <cuda_bf16.h>
#include <cstddef>
#include <cstdint>

#define DIMN   512
#define NSLOT  32
#define BATCH  32
#define TSTEPS 2048
#define RANKS  4      // cluster size = d-chunks
#define BPC    2      // batches per CTA
#define DCH    128    // d columns per CTA
#define NTHR   512
#define VR     8      // virtual ranks = RANKS * 2 halves

// ---------------- scratch ----------------
__device__ float g_pre[(size_t)BATCH * TSTEPS * DIMN];
__device__ float g_WhP[DIMN * DIMN];   // packed: float4 idx = k4*DIMN + d
__device__ float g_WwP[DIMN * DIMN];

// ---------------- PTX helpers ----------------
__device__ __forceinline__ uint32_t smem_u32(const void* p) {
    uint32_t a;
    asm("{ .reg .u64 t; cvta.to.shared.u64 t, %1; cvt.u32.u64 %0, t; }"
        : "=r"(a) : "l"(p));
    return a;
}
__device__ __forceinline__ uint32_t mapa_rank(uint32_t laddr, uint32_t rank) {
    uint32_t r;
    asm("mapa.shared::cluster.u32 %0, %1, %2;" : "=r"(r) : "r"(laddr), "r"(rank));
    return r;
}
__device__ __forceinline__ void sts_cluster_f32(uint32_t addr, float v) {
    asm volatile("st.shared::cluster.f32 [%0], %1;" :: "r"(addr), "f"(v) : "memory");
}
__device__ __forceinline__ void sts_cluster_f32x2(uint32_t addr, float a, float b) {
    asm volatile("st.shared::cluster.v2.f32 [%0], {%1, %2};"
                 :: "r"(addr), "f"(a), "f"(b) : "memory");
}
__device__ __forceinline__ void mbar_init(uint32_t addr, uint32_t cnt) {
    asm volatile("mbarrier.init.shared.b64 [%0], %1;" :: "r"(addr), "r"(cnt) : "memory");
}
__device__ __forceinline__ void mbar_arrive_cl(uint32_t remAddr) {
    asm volatile("mbarrier.arrive.release.cluster.shared::cluster.b64 _, [%0];"
                 :: "r"(remAddr) : "memory");
}
__device__ __forceinline__ void mbar_wait_parity_cl(uint32_t addr, uint32_t parity) {
    asm volatile(
        "{\n\t"
        ".reg .pred P;\n\t"
        "LAB_WAIT_%=:\n\t"
        "mbarrier.try_wait.parity.acquire.cluster.shared::cta.b64 P, [%0], %1, 0x989680;\n\t"
        "@P bra.uni LAB_DONE_%=;\n\t"
        "bra.uni LAB_WAIT_%=;\n\t"
        "LAB_DONE_%=:\n\t"
        "}"
        :: "r"(addr), "r"(parity) : "memory");
}
__device__ __forceinline__ void cluster_sync_() {
    asm volatile("barrier.cluster.arrive.aligned;\n\tbarrier.cluster.wait.aligned;" ::: "memory");
}

__global__ void dummy_k() {}

// ---------------- weight packing ----------------
__global__ void pack_weights(const float* __restrict__ Wh,
                             const float* __restrict__ Ww) {
    int idx = blockIdx.x * blockDim.x + threadIdx.x;
    if (idx >= DIMN * DIMN) return;
    int d = idx / DIMN;
    int k = idx % DIMN;
    int dst = ((k >> 2) * DIMN + d) * 4 + (k & 3);
    g_WhP[dst] = Wh[idx];
    g_WwP[dst] = Ww[idx];
}

// ---------------- pre-GEMM ----------------
__global__ __launch_bounds__(256) void gemm_pre(
    const float* __restrict__ X,
    const float* __restrict__ W,
    const float* __restrict__ bias)
{
    __shared__ float As[8][128];
    __shared__ float Bs[8][64];
    const int tid = threadIdx.x;
    const int m0 = blockIdx.y * 128;
    const int n0 = blockIdx.x * 64;
    const int trow = tid >> 4;
    const int tcol = tid & 15;
    float acc[8][4];
#pragma unroll
    for (int i = 0; i < 8; ++i)
#pragma unroll
        for (int j = 0; j < 4; ++j) acc[i][j] = 0.f;
    const int a_m  = tid >> 1;
    const int a_k4 = (tid & 1) * 4;
    for (int k0 = 0; k0 < DIMN; k0 += 8) {
        float4 av = *reinterpret_cast<const float4*>(
            X + (size_t)(m0 + a_m) * DIMN + k0 + a_k4);
        As[a_k4 + 0][a_m] = av.x;
        As[a_k4 + 1][a_m] = av.y;
        As[a_k4 + 2][a_m] = av.z;
        As[a_k4 + 3][a_m] = av.w;
        if (tid < 128) {
            int bn  = tid >> 1;
            int bk4 = (tid & 1) * 4;
            float4 bv = *reinterpret_cast<const float4*>(
                W + (size_t)(n0 + bn) * DIMN + k0 + bk4);
            Bs[bk4 + 0][bn] = bv.x;
            Bs[bk4 + 1][bn] = bv.y;
            Bs[bk4 + 2][bn] = bv.z;
            Bs[bk4 + 3][bn] = bv.w;
        }
        __syncthreads();
#pragma unroll
        for (int kk = 0; kk < 8; ++kk) {
            float4 ra0 = *reinterpret_cast<const float4*>(&As[kk][trow * 8]);
            float4 ra1 = *reinterpret_cast<const float4*>(&As[kk][trow * 8 + 4]);
            float4 rb  = *reinterpret_cast<const float4*>(&Bs[kk][tcol * 4]);
            float ra[8] = {ra0.x, ra0.y, ra0.z, ra0.w, ra1.x, ra1.y, ra1.z, ra1.w};
            float rbv[4] = {rb.x, rb.y, rb.z, rb.w};
#pragma unroll
            for (int i = 0; i < 8; ++i)
#pragma unroll
                for (int j = 0; j < 4; ++j) acc[i][j] += ra[i] * rbv[j];
        }
        __syncthreads();
    }
    float4 bj = *reinterpret_cast<const float4*>(bias + n0 + tcol * 4);
#pragma unroll
    for (int i = 0; i < 8; ++i) {
        float4 v;
        v.x = acc[i][0] + bj.x;
        v.y = acc[i][1] + bj.y;
        v.z = acc[i][2] + bj.z;
        v.w = acc[i][3] + bj.w;
        *reinterpret_cast<float4*>(
            &g_pre[(size_t)(m0 + trow * 8 + i) * DIMN + n0 + tcol * 4]) = v;
    }
}

// ---------------- exact entmax-1.5 (warp-collective, lane = slot) ----------------
__device__ __forceinline__ float entmax_coef(float raw, float* __restrict__ sb, int lane) {
    const unsigned FULL = 0xffffffffu;
    float z = raw * 0.5f;
    float m = z;
#pragma unroll
    for (int o = 16; o > 0; o >>= 1) m = fmaxf(m, __shfl_xor_sync(FULL, m, o));
    z -= m;
    int rank = 0;
#pragma unroll
    for (int j = 0; j < 32; ++j) {
        float zj = __shfl_sync(FULL, z, j);
        rank += (zj > z) || (zj == z && j < lane);
    }
    sb[rank] = z;
    __syncwarp();
    float zs = sb[lane];
    float cs = zs, cq = zs * zs;
#pragma unroll
    for (int o = 1; o < 32; o <<= 1) {
        float a  = __shfl_up_sync(FULL, cs, o);
        float bq = __shfl_up_sync(FULL, cq, o);
        if (lane >= o) { cs += a; cq += bq; }
    }
    float k    = (float)(lane + 1);
    float mean = cs / k;
    float msq  = cq / k;
    float ss   = k * (msq - mean * mean);
    float delta = fmaxf((1.f - ss) / k, 0.f);
    float tau   = mean - sqrtf(delta);
    unsigned sup = __ballot_sync(FULL, tau <= zs);
    int kstar = __popc(sup) - 1;
    float tau_star = __shfl_sync(FULL, tau, kstar);
    float p = fmaxf(z - tau_star, 0.f);
    return p * p;
}

// ---------------- GEMV partials: 16 warps = 16 k-segments of 32 ----------------
// 2 batches, 128 d per CTA; lane covers d = lane + {0,32,64,96}
__device__ __forceinline__ void gemv16(const float* __restrict__ Wp,
                                       const float4* __restrict__ xw4, // [2][128]
                                       float* __restrict__ part,
                                       int wid, int lane, int dbase) {
    const float4* W4 = reinterpret_cast<const float4*>(Wp)
                       + (size_t)(wid * 8) * DIMN + dbase + lane;
    float a00 = 0.f, a01 = 0.f, a10 = 0.f, a11 = 0.f;
    float a20 = 0.f, a21 = 0.f, a30 = 0.f, a31 = 0.f;
#pragma unroll
    for (int i = 0; i < 8; ++i) {
        float4 k0 = xw4[0 * 128 + wid * 8 + i];
        float4 k1 = xw4[1 * 128 + wid * 8 + i];
        float4 w0 = W4[(size_t)i * DIMN];
        float4 w1 = W4[(size_t)i * DIMN + 32];
        float4 w2 = W4[(size_t)i * DIMN + 64];
        float4 w3 = W4[(size_t)i * DIMN + 96];
        a00 += w0.x * k0.x + w0.y * k0.y + w0.z * k0.z + w0.w * k0.w;
        a01 += w0.x * k1.x + w0.y * k1.y + w0.z * k1.z + w0.w * k1.w;
        a10 += w1.x * k0.x + w1.y * k0.y + w1.z * k0.z + w1.w * k0.w;
        a11 += w1.x * k1.x + w1.y * k1.y + w1.z * k1.z + w1.w * k1.w;
        a20 += w2.x * k0.x + w2.y * k0.y + w2.z * k0.z + w2.w * k0.w;
        a21 += w2.x * k1.x + w2.y * k1.y + w2.z * k1.z + w2.w * k1.w;
        a30 += w3.x * k0.x + w3.y * k0.y + w3.z * k0.z + w3.w * k0.w;
        a31 += w3.x * k1.x + w3.y * k1.y + w3.z * k1.z + w3.w * k1.w;
    }
    float* pp = part + wid * 256 + lane;
    pp[0]        = a00;  pp[128]       = a01;
    pp[32]       = a10;  pp[128 + 32]  = a11;
    pp[64]       = a20;  pp[128 + 64]  = a21;
    pp[96]       = a30;  pp[128 + 96]  = a31;
}

// ---------------- SMEM float offsets ----------------
#define SM_PART   0       // [16][2][128]         4096
#define SM_XW     4096    // [2 par][2 b][512]    2048
#define SM_WVEC   6144    // [2][128]             256
#define SM_COEFA  6400    // [2][32]              64
#define SM_COEFB  6464    // [2][32]              64
#define SM_SORT   6528    // [2][32]              64
#define SM_TAPE   6592    // [2][32][129]         8256
#define SM_XC     14848   // [2 par][8 vr][2 b][66]  2112
#define SM_MBARB  16960   // u64
#define SM_MBARC  16962   // u64
#define SM_FLOATS 16964

// ---------------- persistent recurrence: cluster-4, BPC=2, DCH=128 ------------
__global__ void __launch_bounds__(NTHR, 1) __cluster_dims__(RANKS, 1, 1)
recur14(const float* __restrict__ tape0,
        const float* __restrict__ work0,
        float* __restrict__ out_hseq,
        float* __restrict__ out_tape,
        float* __restrict__ out_hlast)
{
    extern __shared__ float sm[];
    float* part  = sm + SM_PART;
    float* xw    = sm + SM_XW;
    float* wvec  = sm + SM_WVEC;
    float* coefA = sm + SM_COEFA;
    float* coefB = sm + SM_COEFB;
    float* sortb = sm + SM_SORT;
    float* tape  = sm + SM_TAPE;
    float* xc    = sm + SM_XC;

    const int tid  = threadIdx.x;
    const int lane = tid & 31;
    const int wid  = tid >> 5;
    const int rk   = blockIdx.x & (RANKS - 1);
    const int bg   = blockIdx.x >> 2;          // 16 batch groups
    const int b0   = bg * BPC;
    const int dbase = rk * DCH;
    const float invsd = 0.044194173824159216f;  // 1/sqrt(512)

    const uint32_t sbase = smem_u32(sm);
    const uint32_t a_xw  = sbase + SM_XW * 4u;
    const uint32_t a_xc  = sbase + SM_XC * 4u;
    const uint32_t a_mbB = sbase + SM_MBARB * 4u;
    const uint32_t a_mbC = sbase + SM_MBARC * 4u;

    if (tid == 0) {
        mbar_init(a_mbB, RANKS);
        mbar_init(a_mbC, RANKS);
    }

    // ---- prologue loads ----
    for (int i = tid; i < BPC * NSLOT * DCH; i += NTHR) {      // 8192
        int b = i >> 12;
        int n = (i >> 7) & 31;
        int d = i & 127;
        tape[(b * NSLOT + n) * 129 + d] =
            tape0[((size_t)(b0 + b) * NSLOT + n) * DIMN + dbase + d];
    }
    for (int i = tid; i < BPC * DIMN; i += NTHR) {             // 1024
        int b = i >> 9;
        int k = i & 511;
        xw[b * DIMN + k] = work0[(size_t)(b0 + b) * DIMN + k];
    }
    __syncthreads();
    cluster_sync_();

    // ---- initial read-scores exchange (parity 0) ----
    // warps 0-3: (b = wid&1, half = wid>>1) 64-d half dots; vrank = rk*2+half
    if (wid < 4) {
        const int b = wid & 1, half = wid >> 1;
        const int vr = rk * 2 + half;
        const float* tr = tape + (b * NSLOT + lane) * 129 + half * 64;
        const float* wk = xw + b * DIMN + dbase + half * 64;
        float s = 0.f;
#pragma unroll
        for (int d = 0; d < 64; ++d) s += tr[d] * wk[d];
        uint32_t off = a_xc + (unsigned)(vr * 132 + b * 66 + 2 * lane) * 4u;
#pragma unroll
        for (int p = 0; p < RANKS; ++p) sts_cluster_f32(mapa_rank(off, p), s);
    }
    __syncthreads();
    if (tid == 0) {
#pragma unroll
        for (int p = 0; p < RANKS; ++p) mbar_arrive_cl(mapa_rank(a_mbC, p));
    }
    mbar_wait_parity_cl(a_mbC, 0u);
    if (wid < BPC) {
        const int b = wid;
        const float* base = xc + b * 66 + 2 * lane;
        float s = 0.f;
#pragma unroll
        for (int vr = 0; vr < VR; ++vr) s += base[vr * 132];
        coefA[b * 32 + lane] = entmax_coef(s * invsd, sortb + b * 32, lane);
    }
    __syncthreads();

    // initial pre prefetch (t=0): tid<256 -> (b = tid>>7, d = tid&127)
    float pre_reg = 0.f;
    if (tid < 256) {
        const int b = tid >> 7, d = tid & 127;
        pre_reg = __ldcs(&g_pre[((size_t)(b0 + b) * TSTEPS) * DIMN + dbase + d]);
    }

    for (int t = 0; t < TSTEPS; ++t) {
        const int oldi = t & 1;
        const int ni   = oldi ^ 1;
        const int cp   = (t + 1) & 1;
        const int bp   = t & 1;

        // ---- A: W_h GEMV partials on h(t-1) ----
        gemv16(g_WhP, reinterpret_cast<const float4*>(xw + oldi * 1024),
               part, wid, lane, dbase);
        __syncthreads();

        // ---- F: finish h(t) (tid<256: b=tid>>7, d=tid&127); push to 4 ranks ----
        if (tid < 256) {
            const int b = tid >> 7, d = tid & 127;
            float acc = pre_reg;
#pragma unroll
            for (int s = 0; s < 16; ++s) acc += part[s * 256 + b * 128 + d];
            const float* tr = tape + b * NSLOT * 129 + d;
            const float* cf = coefA + b * 32;
#pragma unroll 8
            for (int n = 0; n < NSLOT; ++n) acc += cf[n] * tr[n * 129];
            float h = tanhf(acc);
            __stcs(&out_hseq[((size_t)(b0 + b) * TSTEPS + t) * DIMN + dbase + d], h);
            uint32_t off = a_xw + (unsigned)(ni * 1024 + b * DIMN + dbase + d) * 4u;
#pragma unroll
            for (int p = 0; p < RANKS; ++p) sts_cluster_f32(mapa_rank(off, p), h);
            int tn = (t + 1 < TSTEPS) ? t + 1 : t;
            pre_reg = __ldcs(&g_pre[((size_t)(b0 + b) * TSTEPS + tn) * DIMN + dbase + d]);
        }
        __syncthreads();
        if (tid == 0) {
#pragma unroll
            for (int p = 0; p < RANKS; ++p) mbar_arrive_cl(mapa_rank(a_mbB, p));
        }
        mbar_wait_parity_cl(a_mbB, (uint32_t)bp);

        // ---- H: W_w GEMV partials on h(t) ----
        gemv16(g_WwP, reinterpret_cast<const float4*>(xw + ni * 1024),
               part, wid, lane, dbase);
        __syncthreads();

        // ---- I: reduce wvec (tid<256) ----
        if (tid < 256) {
            const int b = tid >> 7, d = tid & 127;
            float acc = 0.f;
#pragma unroll
            for (int s = 0; s < 16; ++s) acc += part[s * 256 + b * 128 + d];
            wvec[b * 128 + d] = acc;
        }
        __syncthreads();

        // ---- J: scores; warps 0-3 (sA,sB half-dots), warps 4-7 (sC halves) ----
        if (wid < 4) {
            const int b = wid & 1, half = wid >> 1;
            const int vr = rk * 2 + half;
            const float* tr = tape + (b * NSLOT + lane) * 129 + half * 64;
            const float* wv = wvec + b * 128 + half * 64;
            const float* hh = xw + ni * 1024 + b * DIMN + dbase + half * 64;
            float sA = 0.f, sB = 0.f;
#pragma unroll
            for (int d = 0; d < 64; ++d) {
                float tv = tr[d];
                sA += tv * wv[d];
                sB += tv * hh[d];
            }
            uint32_t off = a_xc + (unsigned)(cp * 1056 + vr * 132 + b * 66 + 2 * lane) * 4u;
#pragma unroll
            for (int p = 0; p < RANKS; ++p) sts_cluster_f32x2(mapa_rank(off, p), sA, sB);
        } else if (wid < 8) {
            const int j = wid - 4;
            const int b = j & 1, half = j >> 1;
            const int vr = rk * 2 + half;
            const float* wv = wvec + b * 128 + half * 64;
            const float* hh = xw + ni * 1024 + b * DIMN + dbase + half * 64;
            float v = wv[lane] * hh[lane] + wv[32 + lane] * hh[32 + lane];
#pragma unroll
            for (int o = 16; o > 0; o >>= 1) v += __shfl_xor_sync(0xffffffffu, v, o);
            if (lane == 0) {
                uint32_t off = a_xc + (unsigned)(cp * 1056 + vr * 132 + b * 66 + 64) * 4u;
#pragma unroll
                for (int p = 0; p < RANKS; ++p) sts_cluster_f32(mapa_rank(off, p), v);
            }
        }
        __syncthreads();
        if (tid == 0) {
#pragma unroll
            for (int p = 0; p < RANKS; ++p) mbar_arrive_cl(mapa_rank(a_mbC, p));
        }
        mbar_wait_parity_cl(a_mbC, (uint32_t)cp);

        // ---- D: reduce over 8 vranks; beta; alpha(t+1) via score recurrence ----
        if (wid < BPC) {
            const int b = wid;
            const float* base = xc + cp * 1056 + b * 66;
            float sA = 0.f, sB = 0.f, sC = 0.f;
#pragma unroll
            for (int vr = 0; vr < VR; ++vr) {
                float2 pr = *reinterpret_cast<const float2*>(base + vr * 132 + 2 * lane);
                sA += pr.x;
                sB += pr.y;
                sC += base[vr * 132 + 64];
            }
            float beta = entmax_coef(sA * invsd, sortb + b * 32, lane);
            coefB[b * 32 + lane] = beta;
            float rnext = ((1.f - beta) * sB + beta * sC) * invsd;
            coefA[b * 32 + lane] = entmax_coef(rnext, sortb + b * 32, lane);
        }
        __syncthreads();

        // ---- E: tape convex update (16 warps: b = wid&1, 4-slot group, 4 d/lane) ----
        {
            const int b = wid & 1;
            const int n0 = (wid >> 1) * 4;
            const float* wv = wvec + b * 128;
            const float* cf = coefB + b * 32 + n0;
            float* tb = tape + (b * NSLOT + n0) * 129;
#pragma unroll
            for (int n = 0; n < 4; ++n) {
                float bt = cf[n], omb = 1.f - bt;
                float* row = tb + n * 129;
                row[lane]      = row[lane]      * omb + bt * wv[lane];
                row[lane + 32] = row[lane + 32] * omb + bt * wv[lane + 32];
                row[lane + 64] = row[lane + 64] * omb + bt * wv[lane + 64];
                row[lane + 96] = row[lane + 96] * omb + bt * wv[lane + 96];
            }
        }
        __syncthreads();
    }

    // ---- final outputs ----
    for (int i = tid; i < BPC * NSLOT * DCH; i += NTHR) {
        int b = i >> 12;
        int n = (i >> 7) & 31;
        int d = i & 127;
        out_tape[((size_t)(b0 + b) * NSLOT + n) * DIMN + dbase + d] =
            tape[(b * NSLOT + n) * 129 + d];
    }
    if (tid < 256) {
        const int b = tid >> 7, d = tid & 127;
        // h(2047): ni at t=2047 is 0
        out_hlast[(size_t)(b0 + b) * DIMN + dbase + d] = xw[b * DIMN + dbase + d];
    }
    cluster_sync_();
}

// ---------------- launch ----------------
extern "C" void kernel_launch(void* const* d_in, const int* in_sizes, int n_in,
                              void* d_out, int out_size) {
    const float* x     = (const float*)d_in[0];
    const float* tape0 = (const float*)d_in[1];
    const float* work0 = (const float*)d_in[2];
    const float* Wh    = (const float*)d_in[3];
    const float* Wx    = (const float*)d_in[4];
    const float* bh    = (const float*)d_in[5];
    const float* Ww    = (const float*)d_in[6];

    float* out       = (float*)d_out;
    float* out_hseq  = out;
    float* out_tape  = out + (size_t)BATCH * TSTEPS * DIMN;
    float* out_hlast = out_tape + (size_t)BATCH * NSLOT * DIMN;

    dummy_k<<<1, 32>>>();

    pack_weights<<<(DIMN * DIMN + 511) / 512, 512>>>(Wh, Ww);

    dim3 ggrid(DIMN / 64, (BATCH * TSTEPS) / 128);
    gemm_pre<<<ggrid, 256>>>(x, Wx, bh);

    const int smem_bytes = SM_FLOATS * 4 + 16;   // ~68 KB
    cudaFuncSetAttribute(recur14, cudaFuncAttributeMaxDynamicSharedMemorySize, smem_bytes);
    recur14<<<(BATCH / BPC) * RANKS, NTHR, smem_bytes>>>(
        tape0, work0, out_hseq, out_tape, out_hlast);
}

// round 15
// speedup vs baseline: 2.7975x; 1.0106x over previous
#include <cuda_runtime.h>
#include <cuda_bf16.h>
#include <cstddef>
#include <cstdint>

#define DIMN   512
#define NSLOT  32
#define BATCH  32
#define TSTEPS 2048
#define RANKS  8      // cluster size = d-chunks
#define BPC    4      // batches per CTA
#define DCH    64     // d columns per CTA
#define NTHR   512

// ---------------- scratch ----------------
__device__ float g_pre[(size_t)BATCH * TSTEPS * DIMN];
__device__ float g_WhP[DIMN * DIMN];   // packed: float4 idx = k4*DIMN + d
__device__ float g_WwP[DIMN * DIMN];

// ---------------- PTX helpers ----------------
__device__ __forceinline__ uint32_t smem_u32(const void* p) {
    uint32_t a;
    asm("{ .reg .u64 t; cvta.to.shared.u64 t, %1; cvt.u32.u64 %0, t; }"
        : "=r"(a) : "l"(p));
    return a;
}
__device__ __forceinline__ uint32_t mapa_rank(uint32_t laddr, uint32_t rank) {
    uint32_t r;
    asm("mapa.shared::cluster.u32 %0, %1, %2;" : "=r"(r) : "r"(laddr), "r"(rank));
    return r;
}
__device__ __forceinline__ void sts_cluster_f32(uint32_t addr, float v) {
    asm volatile("st.shared::cluster.f32 [%0], %1;" :: "r"(addr), "f"(v) : "memory");
}
__device__ __forceinline__ void sts_cluster_f32x2(uint32_t addr, float a, float b) {
    asm volatile("st.shared::cluster.v2.f32 [%0], {%1, %2};"
                 :: "r"(addr), "f"(a), "f"(b) : "memory");
}
__device__ __forceinline__ void mbar_init(uint32_t addr, uint32_t cnt) {
    asm volatile("mbarrier.init.shared.b64 [%0], %1;" :: "r"(addr), "r"(cnt) : "memory");
}
__device__ __forceinline__ void mbar_arrive_cl(uint32_t remAddr) {
    asm volatile("mbarrier.arrive.release.cluster.shared::cluster.b64 _, [%0];"
                 :: "r"(remAddr) : "memory");
}
__device__ __forceinline__ void mbar_wait_parity_cl(uint32_t addr, uint32_t parity) {
    asm volatile(
        "{\n\t"
        ".reg .pred P;\n\t"
        "LAB_WAIT_%=:\n\t"
        "mbarrier.try_wait.parity.acquire.cluster.shared::cta.b64 P, [%0], %1, 0x989680;\n\t"
        "@P bra.uni LAB_DONE_%=;\n\t"
        "bra.uni LAB_WAIT_%=;\n\t"
        "LAB_DONE_%=:\n\t"
        "}"
        :: "r"(addr), "r"(parity) : "memory");
}
__device__ __forceinline__ void cluster_sync_() {
    asm volatile("barrier.cluster.arrive.aligned;\n\tbarrier.cluster.wait.aligned;" ::: "memory");
}

// ---- packed f32x2 FMA (FFMA2) ----
__device__ __forceinline__ void fma2(unsigned long long& acc,
                                     unsigned long long a, unsigned long long b) {
    asm("fma.rn.f32x2 %0, %1, %2, %0;" : "+l"(acc) : "l"(a), "l"(b));
}
__device__ __forceinline__ unsigned long long f4lo(const float4& v) {
    return reinterpret_cast<const unsigned long long*>(&v)[0];
}
__device__ __forceinline__ unsigned long long f4hi(const float4& v) {
    return reinterpret_cast<const unsigned long long*>(&v)[1];
}
__device__ __forceinline__ float hadd2(unsigned long long v) {
    float2 f;
    asm("mov.b64 {%0, %1}, %2;" : "=f"(f.x), "=f"(f.y) : "l"(v));
    return f.x + f.y;
}

__global__ void dummy_k() {}

// ---------------- weight packing ----------------
__global__ void pack_weights(const float* __restrict__ Wh,
                             const float* __restrict__ Ww) {
    int idx = blockIdx.x * blockDim.x + threadIdx.x;
    if (idx >= DIMN * DIMN) return;
    int d = idx / DIMN;
    int k = idx % DIMN;
    int dst = ((k >> 2) * DIMN + d) * 4 + (k & 3);
    g_WhP[dst] = Wh[idx];
    g_WwP[dst] = Ww[idx];
}

// ---------------- pre-GEMM ----------------
__global__ __launch_bounds__(256) void gemm_pre(
    const float* __restrict__ X,
    const float* __restrict__ W,
    const float* __restrict__ bias)
{
    __shared__ float As[8][128];
    __shared__ float Bs[8][64];
    const int tid = threadIdx.x;
    const int m0 = blockIdx.y * 128;
    const int n0 = blockIdx.x * 64;
    const int trow = tid >> 4;
    const int tcol = tid & 15;
    float acc[8][4];
#pragma unroll
    for (int i = 0; i < 8; ++i)
#pragma unroll
        for (int j = 0; j < 4; ++j) acc[i][j] = 0.f;
    const int a_m  = tid >> 1;
    const int a_k4 = (tid & 1) * 4;
    for (int k0 = 0; k0 < DIMN; k0 += 8) {
        float4 av = *reinterpret_cast<const float4*>(
            X + (size_t)(m0 + a_m) * DIMN + k0 + a_k4);
        As[a_k4 + 0][a_m] = av.x;
        As[a_k4 + 1][a_m] = av.y;
        As[a_k4 + 2][a_m] = av.z;
        As[a_k4 + 3][a_m] = av.w;
        if (tid < 128) {
            int bn  = tid >> 1;
            int bk4 = (tid & 1) * 4;
            float4 bv = *reinterpret_cast<const float4*>(
                W + (size_t)(n0 + bn) * DIMN + k0 + bk4);
            Bs[bk4 + 0][bn] = bv.x;
            Bs[bk4 + 1][bn] = bv.y;
            Bs[bk4 + 2][bn] = bv.z;
            Bs[bk4 + 3][bn] = bv.w;
        }
        __syncthreads();
#pragma unroll
        for (int kk = 0; kk < 8; ++kk) {
            float4 ra0 = *reinterpret_cast<const float4*>(&As[kk][trow * 8]);
            float4 ra1 = *reinterpret_cast<const float4*>(&As[kk][trow * 8 + 4]);
            float4 rb  = *reinterpret_cast<const float4*>(&Bs[kk][tcol * 4]);
            float ra[8] = {ra0.x, ra0.y, ra0.z, ra0.w, ra1.x, ra1.y, ra1.z, ra1.w};
            float rbv[4] = {rb.x, rb.y, rb.z, rb.w};
#pragma unroll
            for (int i = 0; i < 8; ++i)
#pragma unroll
                for (int j = 0; j < 4; ++j) acc[i][j] += ra[i] * rbv[j];
        }
        __syncthreads();
    }
    float4 bj = *reinterpret_cast<const float4*>(bias + n0 + tcol * 4);
#pragma unroll
    for (int i = 0; i < 8; ++i) {
        float4 v;
        v.x = acc[i][0] + bj.x;
        v.y = acc[i][1] + bj.y;
        v.z = acc[i][2] + bj.z;
        v.w = acc[i][3] + bj.w;
        *reinterpret_cast<float4*>(
            &g_pre[(size_t)(m0 + trow * 8 + i) * DIMN + n0 + tcol * 4]) = v;
    }
}

// ---------------- exact entmax-1.5 (warp-collective, lane = slot) ----------------
__device__ __forceinline__ float entmax_coef(float raw, float* __restrict__ sb, int lane) {
    const unsigned FULL = 0xffffffffu;
    float z = raw * 0.5f;
    float m = z;
#pragma unroll
    for (int o = 16; o > 0; o >>= 1) m = fmaxf(m, __shfl_xor_sync(FULL, m, o));
    z -= m;
    int rank = 0;
#pragma unroll
    for (int j = 0; j < 32; ++j) {
        float zj = __shfl_sync(FULL, z, j);
        rank += (zj > z) || (zj == z && j < lane);
    }
    sb[rank] = z;
    __syncwarp();
    float zs = sb[lane];
    float cs = zs, cq = zs * zs;
#pragma unroll
    for (int o = 1; o < 32; o <<= 1) {
        float a  = __shfl_up_sync(FULL, cs, o);
        float bq = __shfl_up_sync(FULL, cq, o);
        if (lane >= o) { cs += a; cq += bq; }
    }
    float k    = (float)(lane + 1);
    float mean = cs / k;
    float msq  = cq / k;
    float ss   = k * (msq - mean * mean);
    float delta = fmaxf((1.f - ss) / k, 0.f);
    float tau   = mean - sqrtf(delta);
    unsigned sup = __ballot_sync(FULL, tau <= zs);
    int kstar = __popc(sup) - 1;
    float tau_star = __shfl_sync(FULL, tau, kstar);
    float p = fmaxf(z - tau_star, 0.f);
    return p * p;
}

// ---------------- GEMV partials via FFMA2: 16 warps = 16 k-segments of 32 ------
// lane covers d = lane and d = lane+32; 4 batches; k packed in f32x2 pairs
__device__ __forceinline__ void gemv16(const float* __restrict__ Wp,
                                       const float4* __restrict__ xw4, // [4][128]
                                       float* __restrict__ part,
                                       int wid, int lane, int dbase) {
    const float4* W4 = reinterpret_cast<const float4*>(Wp)
                       + (size_t)(wid * 8) * DIMN + dbase + lane;
    unsigned long long a0 = 0ull, a1 = 0ull, a2 = 0ull, a3 = 0ull;
    unsigned long long b0 = 0ull, b1 = 0ull, b2 = 0ull, b3 = 0ull;
#pragma unroll
    for (int i = 0; i < 8; ++i) {
        float4 w0 = W4[(size_t)i * DIMN];
        float4 w1 = W4[(size_t)i * DIMN + 32];
        float4 k0 = xw4[0 * 128 + wid * 8 + i];
        float4 k1 = xw4[1 * 128 + wid * 8 + i];
        float4 k2 = xw4[2 * 128 + wid * 8 + i];
        float4 k3 = xw4[3 * 128 + wid * 8 + i];
        unsigned long long w0l = f4lo(w0), w0h = f4hi(w0);
        unsigned long long w1l = f4lo(w1), w1h = f4hi(w1);
        fma2(a0, w0l, f4lo(k0));  fma2(a0, w0h, f4hi(k0));
        fma2(a1, w0l, f4lo(k1));  fma2(a1, w0h, f4hi(k1));
        fma2(a2, w0l, f4lo(k2));  fma2(a2, w0h, f4hi(k2));
        fma2(a3, w0l, f4lo(k3));  fma2(a3, w0h, f4hi(k3));
        fma2(b0, w1l, f4lo(k0));  fma2(b0, w1h, f4hi(k0));
        fma2(b1, w1l, f4lo(k1));  fma2(b1, w1h, f4hi(k1));
        fma2(b2, w1l, f4lo(k2));  fma2(b2, w1h, f4hi(k2));
        fma2(b3, w1l, f4lo(k3));  fma2(b3, w1h, f4hi(k3));
    }
    float* pp = part + wid * 256 + lane;
    pp[0]   = hadd2(a0);  pp[64]  = hadd2(a1);
    pp[128] = hadd2(a2);  pp[192] = hadd2(a3);
    pp[32]  = hadd2(b0);  pp[96]  = hadd2(b1);
    pp[160] = hadd2(b2);  pp[224] = hadd2(b3);
}

// ---------------- SMEM float offsets (R5 layout) ----------------
#define SM_PART   0       // [16][4][64]          4096
#define SM_XW     4096    // [2][4][512]          4096
#define SM_WVEC   8192    // [4][64]              256
#define SM_COEFA  8448    // [4][32]              128
#define SM_COEFB  8576    // [4][32]              128
#define SM_SORT   8704    // [4][32]              128
#define SM_TAPE   8832    // [4][32][65]          8320
#define SM_XC     17152   // [2][8][4][130]       8320
#define SM_MBARB  25472   // u64
#define SM_MBARC  25474   // u64
#define SM_FLOATS 25476

// ---------------- persistent recurrence (R5 structure + FFMA2 GEMV) ----------
__global__ void __launch_bounds__(NTHR, 1) __cluster_dims__(RANKS, 1, 1)
recur15(const float* __restrict__ tape0,
        const float* __restrict__ work0,
        float* __restrict__ out_hseq,
        float* __restrict__ out_tape,
        float* __restrict__ out_hlast)
{
    extern __shared__ float sm[];
    float* part  = sm + SM_PART;
    float* xw    = sm + SM_XW;
    float* wvec  = sm + SM_WVEC;
    float* coefA = sm + SM_COEFA;
    float* coefB = sm + SM_COEFB;
    float* sortb = sm + SM_SORT;
    float* tape  = sm + SM_TAPE;
    float* xc    = sm + SM_XC;

    const int tid  = threadIdx.x;
    const int lane = tid & 31;
    const int wid  = tid >> 5;
    const int rk   = blockIdx.x & (RANKS - 1);
    const int bg   = blockIdx.x >> 3;
    const int b0   = bg * BPC;
    const int dbase = rk * DCH;
    const float invsd = 0.044194173824159216f;  // 1/sqrt(512)

    const uint32_t sbase = smem_u32(sm);
    const uint32_t a_xw  = sbase + SM_XW * 4u;
    const uint32_t a_xc  = sbase + SM_XC * 4u;
    const uint32_t a_mbB = sbase + SM_MBARB * 4u;
    const uint32_t a_mbC = sbase + SM_MBARC * 4u;

    if (tid == 0) {
        mbar_init(a_mbB, RANKS);
        mbar_init(a_mbC, RANKS);
    }

    // ---- prologue loads ----
    for (int i = tid; i < BPC * NSLOT * DCH; i += NTHR) {
        int b = i >> 11;
        int n = (i >> 6) & 31;
        int d = i & 63;
        tape[(b * NSLOT + n) * 65 + d] =
            tape0[((size_t)(b0 + b) * NSLOT + n) * DIMN + dbase + d];
    }
    for (int i = tid; i < BPC * DIMN; i += NTHR) {
        int b = i >> 9;
        int k = i & 511;
        xw[b * DIMN + k] = work0[(size_t)(b0 + b) * DIMN + k];
    }
    __syncthreads();
    cluster_sync_();

    // ---- initial read-scores exchange (parity 0) ----
    if (wid < 8) {
        const int b = wid & 3, half = wid >> 2;
        const float* tr = tape + (b * NSLOT + lane) * 65 + half * 32;
        const float* wk = xw + b * DIMN + dbase + half * 32;
        float s = 0.f;
#pragma unroll
        for (int d = 0; d < 32; ++d) s += tr[d] * wk[d];
        uint32_t off = a_xc + (unsigned)(rk * 520 + b * 130 + 2 * (half * 32 + lane)) * 4u;
#pragma unroll
        for (int p = 0; p < RANKS; ++p) sts_cluster_f32(mapa_rank(off, p), s);
    }
    __syncthreads();
    if (tid == 0) {
#pragma unroll
        for (int p = 0; p < RANKS; ++p) mbar_arrive_cl(mapa_rank(a_mbC, p));
    }
    mbar_wait_parity_cl(a_mbC, 0u);
    if (wid < BPC) {
        const int b = wid;
        const float* base = xc + b * 130 + 2 * lane;
        float s = 0.f;
#pragma unroll
        for (int r = 0; r < RANKS; ++r) s += base[r * 520] + base[r * 520 + 64];
        coefA[b * 32 + lane] = entmax_coef(s * invsd, sortb + b * 32, lane);
    }
    __syncthreads();

    for (int t = 0; t < TSTEPS; ++t) {
        const int oldi = t & 1;
        const int ni   = oldi ^ 1;
        const int csl  = (t + 1) & 1;

        // prefetch pre (tid<256: b=tid>>6, d=tid&63)
        float pre_v = 0.f;
        if (tid < 256) {
            pre_v = __ldcs(&g_pre[((size_t)(b0 + (tid >> 6)) * TSTEPS + t) * DIMN
                                  + dbase + (tid & 63)]);
        }

        // ---- phase A: W_h GEMV partials (16 warps, FFMA2) ----
        gemv16(g_WhP, reinterpret_cast<const float4*>(xw + oldi * 2048), part,
               wid, lane, dbase);
        __syncthreads();

        // finish h chunk (tid<256): reduce 16 partials + alpha.tape + tanh; push h
        if (tid < 256) {
            const int b = tid >> 6, d = tid & 63;
            float acc = pre_v;
#pragma unroll
            for (int s = 0; s < 16; ++s) acc += part[s * 256 + b * 64 + d];
            const float* tr = tape + b * NSLOT * 65 + d;
            const float* cf = coefA + b * 32;
#pragma unroll 8
            for (int n = 0; n < NSLOT; ++n) acc += cf[n] * tr[n * 65];
            float h = tanhf(acc);
            __stcs(&out_hseq[((size_t)(b0 + b) * TSTEPS + t) * DIMN + dbase + d], h);
            uint32_t off = a_xw + (unsigned)(ni * 2048 + b * DIMN + dbase + d) * 4u;
#pragma unroll
            for (int p = 0; p < RANKS; ++p) sts_cluster_f32(mapa_rank(off, p), h);
        }
        __syncthreads();
        if (tid == 0) {
#pragma unroll
            for (int p = 0; p < RANKS; ++p) mbar_arrive_cl(mapa_rank(a_mbB, p));
        }
        mbar_wait_parity_cl(a_mbB, (uint32_t)(t & 1));

        // ---- phase B: W_w GEMV partials on full h (FFMA2) ----
        gemv16(g_WwP, reinterpret_cast<const float4*>(xw + ni * 2048), part,
               wid, lane, dbase);
        __syncthreads();
        if (tid < 256) {
            const int b = tid >> 6, d = tid & 63;
            float acc = 0.f;
#pragma unroll
            for (int s = 0; s < 16; ++s) acc += part[s * 256 + b * 64 + d];
            wvec[b * 64 + d] = acc;
        }
        __syncthreads();

        // ---- phase C: score partials; warps 0-7: (sA,sB); warps 8-11: sC ----
        if (wid < 8) {
            const int b = wid & 3, half = wid >> 2;
            const float* tr = tape + (b * NSLOT + lane) * 65 + half * 32;
            const float* wv = wvec + b * 64 + half * 32;
            const float* hh = xw + ni * 2048 + b * DIMN + dbase + half * 32;
            float sA = 0.f, sB = 0.f;
#pragma unroll
            for (int d = 0; d < 32; ++d) {
                float tv = tr[d];
                sA += tv * wv[d];
                sB += tv * hh[d];
            }
            uint32_t off = a_xc + (unsigned)(csl * 4160 + rk * 520 + b * 130
                                             + 2 * (half * 32 + lane)) * 4u;
#pragma unroll
            for (int p = 0; p < RANKS; ++p) sts_cluster_f32x2(mapa_rank(off, p), sA, sB);
        } else if (wid < 12) {
            const int b = wid - 8;
            float v = wvec[b * 64 + lane] * xw[ni * 2048 + b * DIMN + dbase + lane]
                    + wvec[b * 64 + 32 + lane] * xw[ni * 2048 + b * DIMN + dbase + 32 + lane];
#pragma unroll
            for (int o = 16; o > 0; o >>= 1) v += __shfl_xor_sync(0xffffffffu, v, o);
            if (lane == 0) {
                uint32_t off = a_xc + (unsigned)(csl * 4160 + rk * 520 + b * 130 + 128) * 4u;
#pragma unroll
                for (int p = 0; p < RANKS; ++p) sts_cluster_f32(mapa_rank(off, p), v);
            }
        }
        __syncthreads();
        if (tid == 0) {
#pragma unroll
            for (int p = 0; p < RANKS; ++p) mbar_arrive_cl(mapa_rank(a_mbC, p));
        }
        mbar_wait_parity_cl(a_mbC, (uint32_t)csl);

        // ---- phase D: reduce; beta = entmax(sA); alpha(t+1) via score recurrence ----
        if (wid < BPC) {
            const int b = wid;
            const float* base = xc + csl * 4160 + b * 130;
            float sA = 0.f, sB = 0.f, sC = 0.f;
#pragma unroll
            for (int r = 0; r < RANKS; ++r) {
                float2 p0 = *reinterpret_cast<const float2*>(base + r * 520 + 2 * lane);
                float2 p1 = *reinterpret_cast<const float2*>(base + r * 520 + 64 + 2 * lane);
                sA += p0.x + p1.x;
                sB += p0.y + p1.y;
                sC += base[r * 520 + 128];
            }
            float beta = entmax_coef(sA * invsd, sortb + b * 32, lane);
            coefB[b * 32 + lane] = beta;
            float rnext = ((1.f - beta) * sB + beta * sC) * invsd;
            coefA[b * 32 + lane] = entmax_coef(rnext, sortb + b * 32, lane);
        }
        __syncthreads();

        // ---- phase E: tape convex update (16 warps: b, 8-slot group) ----
        {
            const int b = wid & 3;
            const int n0 = (wid >> 2) * 8;
            const float* wv = wvec + b * 64;
            const float* cf = coefB + b * 32 + n0;
            float* tb = tape + (b * NSLOT + n0) * 65;
#pragma unroll
            for (int n = 0; n < 8; ++n) {
                float bt = cf[n];
                float omb = 1.f - bt;
                float* tr = tb + n * 65;
                tr[lane]      = tr[lane]      * omb + bt * wv[lane];
                tr[lane + 32] = tr[lane + 32] * omb + bt * wv[lane + 32];
            }
        }
        __syncthreads();
    }

    // ---- final outputs ----
    for (int i = tid; i < BPC * NSLOT * DCH; i += NTHR) {
        int b = i >> 11;
        int n = (i >> 6) & 31;
        int d = i & 63;
        out_tape[((size_t)(b0 + b) * NSLOT + n) * DIMN + dbase + d] =
            tape[(b * NSLOT + n) * 65 + d];
    }
    if (tid < 256) {
        const int b = tid >> 6, d = tid & 63;
        // h(2047): ni at t=2047 is 0
        out_hlast[(size_t)(b0 + b) * DIMN + dbase + d] = xw[b * DIMN + dbase + d];
    }
    cluster_sync_();
}

// ---------------- launch ----------------
extern "C" void kernel_launch(void* const* d_in, const int* in_sizes, int n_in,
                              void* d_out, int out_size) {
    const float* x     = (const float*)d_in[0];
    const float* tape0 = (const float*)d_in[1];
    const float* work0 = (const float*)d_in[2];
    const float* Wh    = (const float*)d_in[3];
    const float* Wx    = (const float*)d_in[4];
    const float* bh    = (const float*)d_in[5];
    const float* Ww    = (const float*)d_in[6];

    float* out       = (float*)d_out;
    float* out_hseq  = out;
    float* out_tape  = out + (size_t)BATCH * TSTEPS * DIMN;
    float* out_hlast = out_tape + (size_t)BATCH * NSLOT * DIMN;

    dummy_k<<<1, 32>>>();

    pack_weights<<<(DIMN * DIMN + 511) / 512, 512>>>(Wh, Ww);

    dim3 ggrid(DIMN / 64, (BATCH * TSTEPS) / 128);
    gemm_pre<<<ggrid, 256>>>(x, Wx, bh);

    const int smem_bytes = SM_FLOATS * 4 + 16;
    cudaFuncSetAttribute(recur15, cudaFuncAttributeMaxDynamicSharedMemorySize, smem_bytes);
    recur15<<<(BATCH / BPC) * RANKS, NTHR, smem_bytes>>>(
        tape0, work0, out_hseq, out_tape, out_hlast);
}

// round 16
// speedup vs baseline: 2.8805x; 1.0297x over previous
#include <cuda_runtime.h>
#include <cuda_bf16.h>
#include <cstddef>
#include <cstdint>

#define DIMN   512
#define NSLOT  32
#define BATCH  32
#define TSTEPS 2048
#define RANKS  8      // cluster size = d-chunks
#define BPC    4      // batches per CTA
#define DCH    64     // d columns per CTA
#define NTHR   512

// ---------------- scratch ----------------
__device__ float g_pre[(size_t)BATCH * TSTEPS * DIMN];
__device__ float g_WhP[DIMN * DIMN];   // packed: float4 idx = k4*DIMN + d
__device__ float g_WwP[DIMN * DIMN];

// ---------------- PTX helpers ----------------
__device__ __forceinline__ uint32_t smem_u32(const void* p) {
    uint32_t a;
    asm("{ .reg .u64 t; cvta.to.shared.u64 t, %1; cvt.u32.u64 %0, t; }"
        : "=r"(a) : "l"(p));
    return a;
}
__device__ __forceinline__ uint32_t mapa_rank(uint32_t laddr, uint32_t rank) {
    uint32_t r;
    asm("mapa.shared::cluster.u32 %0, %1, %2;" : "=r"(r) : "r"(laddr), "r"(rank));
    return r;
}
__device__ __forceinline__ void sts_cluster_f32(uint32_t addr, float v) {
    asm volatile("st.shared::cluster.f32 [%0], %1;" :: "r"(addr), "f"(v) : "memory");
}
__device__ __forceinline__ void sts_cluster_f32x2(uint32_t addr, float a, float b) {
    asm volatile("st.shared::cluster.v2.f32 [%0], {%1, %2};"
                 :: "r"(addr), "f"(a), "f"(b) : "memory");
}
__device__ __forceinline__ void mbar_init(uint32_t addr, uint32_t cnt) {
    asm volatile("mbarrier.init.shared.b64 [%0], %1;" :: "r"(addr), "r"(cnt) : "memory");
}
__device__ __forceinline__ void mbar_arrive_cl(uint32_t remAddr) {
    asm volatile("mbarrier.arrive.release.cluster.shared::cluster.b64 _, [%0];"
                 :: "r"(remAddr) : "memory");
}
__device__ __forceinline__ void mbar_wait_parity_cl(uint32_t addr, uint32_t parity) {
    asm volatile(
        "{\n\t"
        ".reg .pred P;\n\t"
        "LAB_WAIT_%=:\n\t"
        "mbarrier.try_wait.parity.acquire.cluster.shared::cta.b64 P, [%0], %1, 0x989680;\n\t"
        "@P bra.uni LAB_DONE_%=;\n\t"
        "bra.uni LAB_WAIT_%=;\n\t"
        "LAB_DONE_%=:\n\t"
        "}"
        :: "r"(addr), "r"(parity) : "memory");
}
__device__ __forceinline__ void cluster_sync_() {
    asm volatile("barrier.cluster.arrive.aligned;\n\tbarrier.cluster.wait.aligned;" ::: "memory");
}

// ---- packed f32x2 FMA (FFMA2) ----
__device__ __forceinline__ void fma2(unsigned long long& acc,
                                     unsigned long long a, unsigned long long b) {
    asm("fma.rn.f32x2 %0, %1, %2, %0;" : "+l"(acc) : "l"(a), "l"(b));
}
__device__ __forceinline__ unsigned long long f4lo(const float4& v) {
    return reinterpret_cast<const unsigned long long*>(&v)[0];
}
__device__ __forceinline__ unsigned long long f4hi(const float4& v) {
    return reinterpret_cast<const unsigned long long*>(&v)[1];
}
__device__ __forceinline__ float hadd2(unsigned long long v) {
    float2 f;
    asm("mov.b64 {%0, %1}, %2;" : "=f"(f.x), "=f"(f.y) : "l"(v));
    return f.x + f.y;
}

__global__ void dummy_k() {}

// ---------------- weight packing ----------------
__global__ void pack_weights(const float* __restrict__ Wh,
                             const float* __restrict__ Ww) {
    int idx = blockIdx.x * blockDim.x + threadIdx.x;
    if (idx >= DIMN * DIMN) return;
    int d = idx / DIMN;
    int k = idx % DIMN;
    int dst = ((k >> 2) * DIMN + d) * 4 + (k & 3);
    g_WhP[dst] = Wh[idx];
    g_WwP[dst] = Ww[idx];
}

// ---------------- pre-GEMM ----------------
__global__ __launch_bounds__(256) void gemm_pre(
    const float* __restrict__ X,
    const float* __restrict__ W,
    const float* __restrict__ bias)
{
    __shared__ float As[8][128];
    __shared__ float Bs[8][64];
    const int tid = threadIdx.x;
    const int m0 = blockIdx.y * 128;
    const int n0 = blockIdx.x * 64;
    const int trow = tid >> 4;
    const int tcol = tid & 15;
    float acc[8][4];
#pragma unroll
    for (int i = 0; i < 8; ++i)
#pragma unroll
        for (int j = 0; j < 4; ++j) acc[i][j] = 0.f;
    const int a_m  = tid >> 1;
    const int a_k4 = (tid & 1) * 4;
    for (int k0 = 0; k0 < DIMN; k0 += 8) {
        float4 av = *reinterpret_cast<const float4*>(
            X + (size_t)(m0 + a_m) * DIMN + k0 + a_k4);
        As[a_k4 + 0][a_m] = av.x;
        As[a_k4 + 1][a_m] = av.y;
        As[a_k4 + 2][a_m] = av.z;
        As[a_k4 + 3][a_m] = av.w;
        if (tid < 128) {
            int bn  = tid >> 1;
            int bk4 = (tid & 1) * 4;
            float4 bv = *reinterpret_cast<const float4*>(
                W + (size_t)(n0 + bn) * DIMN + k0 + bk4);
            Bs[bk4 + 0][bn] = bv.x;
            Bs[bk4 + 1][bn] = bv.y;
            Bs[bk4 + 2][bn] = bv.z;
            Bs[bk4 + 3][bn] = bv.w;
        }
        __syncthreads();
#pragma unroll
        for (int kk = 0; kk < 8; ++kk) {
            float4 ra0 = *reinterpret_cast<const float4*>(&As[kk][trow * 8]);
            float4 ra1 = *reinterpret_cast<const float4*>(&As[kk][trow * 8 + 4]);
            float4 rb  = *reinterpret_cast<const float4*>(&Bs[kk][tcol * 4]);
            float ra[8] = {ra0.x, ra0.y, ra0.z, ra0.w, ra1.x, ra1.y, ra1.z, ra1.w};
            float rbv[4] = {rb.x, rb.y, rb.z, rb.w};
#pragma unroll
            for (int i = 0; i < 8; ++i)
#pragma unroll
                for (int j = 0; j < 4; ++j) acc[i][j] += ra[i] * rbv[j];
        }
        __syncthreads();
    }
    float4 bj = *reinterpret_cast<const float4*>(bias + n0 + tcol * 4);
#pragma unroll
    for (int i = 0; i < 8; ++i) {
        float4 v;
        v.x = acc[i][0] + bj.x;
        v.y = acc[i][1] + bj.y;
        v.z = acc[i][2] + bj.z;
        v.w = acc[i][3] + bj.w;
        *reinterpret_cast<float4*>(
            &g_pre[(size_t)(m0 + trow * 8 + i) * DIMN + n0 + tcol * 4]) = v;
    }
}

// ---------------- exact entmax-1.5 (warp-collective, lane = slot) ----------------
__device__ __forceinline__ float entmax_coef(float raw, float* __restrict__ sb, int lane) {
    const unsigned FULL = 0xffffffffu;
    float z = raw * 0.5f;
    float m = z;
#pragma unroll
    for (int o = 16; o > 0; o >>= 1) m = fmaxf(m, __shfl_xor_sync(FULL, m, o));
    z -= m;
    int rank = 0;
#pragma unroll
    for (int j = 0; j < 32; ++j) {
        float zj = __shfl_sync(FULL, z, j);
        rank += (zj > z) || (zj == z && j < lane);
    }
    sb[rank] = z;
    __syncwarp();
    float zs = sb[lane];
    float cs = zs, cq = zs * zs;
#pragma unroll
    for (int o = 1; o < 32; o <<= 1) {
        float a  = __shfl_up_sync(FULL, cs, o);
        float bq = __shfl_up_sync(FULL, cq, o);
        if (lane >= o) { cs += a; cq += bq; }
    }
    float k    = (float)(lane + 1);
    float mean = cs / k;
    float msq  = cq / k;
    float ss   = k * (msq - mean * mean);
    float delta = fmaxf((1.f - ss) / k, 0.f);
    float tau   = mean - sqrtf(delta);
    unsigned sup = __ballot_sync(FULL, tau <= zs);
    int kstar = __popc(sup) - 1;
    float tau_star = __shfl_sync(FULL, tau, kstar);
    float p = fmaxf(z - tau_star, 0.f);
    return p * p;
}

// ---------------- GEMV partials via FFMA2: 16 warps = 16 k-segments of 32 ------
__device__ __forceinline__ void gemv16(const float* __restrict__ Wp,
                                       const float4* __restrict__ xw4, // [4][128]
                                       float* __restrict__ part,
                                       int wid, int lane, int dbase) {
    const float4* W4 = reinterpret_cast<const float4*>(Wp)
                       + (size_t)(wid * 8) * DIMN + dbase + lane;
    unsigned long long a0 = 0ull, a1 = 0ull, a2 = 0ull, a3 = 0ull;
    unsigned long long b0 = 0ull, b1 = 0ull, b2 = 0ull, b3 = 0ull;
#pragma unroll
    for (int i = 0; i < 8; ++i) {
        float4 w0 = W4[(size_t)i * DIMN];
        float4 w1 = W4[(size_t)i * DIMN + 32];
        float4 k0 = xw4[0 * 128 + wid * 8 + i];
        float4 k1 = xw4[1 * 128 + wid * 8 + i];
        float4 k2 = xw4[2 * 128 + wid * 8 + i];
        float4 k3 = xw4[3 * 128 + wid * 8 + i];
        unsigned long long w0l = f4lo(w0), w0h = f4hi(w0);
        unsigned long long w1l = f4lo(w1), w1h = f4hi(w1);
        fma2(a0, w0l, f4lo(k0));  fma2(a0, w0h, f4hi(k0));
        fma2(a1, w0l, f4lo(k1));  fma2(a1, w0h, f4hi(k1));
        fma2(a2, w0l, f4lo(k2));  fma2(a2, w0h, f4hi(k2));
        fma2(a3, w0l, f4lo(k3));  fma2(a3, w0h, f4hi(k3));
        fma2(b0, w1l, f4lo(k0));  fma2(b0, w1h, f4hi(k0));
        fma2(b1, w1l, f4lo(k1));  fma2(b1, w1h, f4hi(k1));
        fma2(b2, w1l, f4lo(k2));  fma2(b2, w1h, f4hi(k2));
        fma2(b3, w1l, f4lo(k3));  fma2(b3, w1h, f4hi(k3));
    }
    float* pp = part + wid * 256 + lane;
    pp[0]   = hadd2(a0);  pp[64]  = hadd2(a1);
    pp[128] = hadd2(a2);  pp[192] = hadd2(a3);
    pp[32]  = hadd2(b0);  pp[96]  = hadd2(b1);
    pp[160] = hadd2(b2);  pp[224] = hadd2(b3);
}

// ---------------- SMEM float offsets ----------------
#define SM_PART   0       // [16][4][64]          4096
#define SM_XW     4096    // [2][4][512]          4096
#define SM_WVEC   8192    // [4][64]              256
#define SM_COEFA  8448    // [4][32]              128
#define SM_COEFB  8576    // [4][32]              128
#define SM_SORT   8704    // [4][32]              128
#define SM_TAPE   8832    // [4][32][65]          8320
#define SM_XC     17152   // [2][8][4][66]        4224
#define SM_MBARB  21376   // u64
#define SM_MBARC  21378   // u64
#define SM_FLOATS 21380

// ---------------- persistent recurrence ----------------
__global__ void __launch_bounds__(NTHR, 1) __cluster_dims__(RANKS, 1, 1)
recur16(const float* __restrict__ tape0,
        const float* __restrict__ work0,
        float* __restrict__ out_hseq,
        float* __restrict__ out_tape,
        float* __restrict__ out_hlast)
{
    extern __shared__ float sm[];
    float* part  = sm + SM_PART;
    float* xw    = sm + SM_XW;
    float* wvec  = sm + SM_WVEC;
    float* coefA = sm + SM_COEFA;
    float* coefB = sm + SM_COEFB;
    float* sortb = sm + SM_SORT;
    float* tape  = sm + SM_TAPE;
    float* xc    = sm + SM_XC;

    const int tid  = threadIdx.x;
    const int lane = tid & 31;
    const int wid  = tid >> 5;
    const int rk   = blockIdx.x & (RANKS - 1);
    const int bg   = blockIdx.x >> 3;
    const int b0   = bg * BPC;
    const int dbase = rk * DCH;
    const float invsd = 0.044194173824159216f;  // 1/sqrt(512)

    const uint32_t sbase = smem_u32(sm);
    const uint32_t a_xw  = sbase + SM_XW * 4u;
    const uint32_t a_xc  = sbase + SM_XC * 4u;
    const uint32_t a_mbB = sbase + SM_MBARB * 4u;
    const uint32_t a_mbC = sbase + SM_MBARC * 4u;

    if (tid == 0) {
        mbar_init(a_mbB, RANKS);
        mbar_init(a_mbC, RANKS);
    }

    // ---- prologue loads ----
    for (int i = tid; i < BPC * NSLOT * DCH; i += NTHR) {
        int b = i >> 11;
        int n = (i >> 6) & 31;
        int d = i & 63;
        tape[(b * NSLOT + n) * 65 + d] =
            tape0[((size_t)(b0 + b) * NSLOT + n) * DIMN + dbase + d];
    }
    for (int i = tid; i < BPC * DIMN; i += NTHR) {
        int b = i >> 9;
        int k = i & 511;
        xw[b * DIMN + k] = work0[(size_t)(b0 + b) * DIMN + k];
    }
    __syncthreads();
    cluster_sync_();

    // ---- initial read-scores exchange (parity 0): warps 0-3 full 64-d dots ----
    if (wid < BPC) {
        const int b = wid;
        const float* tr = tape + (b * NSLOT + lane) * 65;
        const float* wk = xw + b * DIMN + dbase;
        float s = 0.f;
#pragma unroll
        for (int d = 0; d < DCH; ++d) s += tr[d] * wk[d];
        uint32_t off = a_xc + (unsigned)(rk * 264 + b * 66 + 2 * lane) * 4u;
#pragma unroll
        for (int p = 0; p < RANKS; ++p) sts_cluster_f32(mapa_rank(off, p), s);
    }
    __syncthreads();
    if (tid == 0) {
#pragma unroll
        for (int p = 0; p < RANKS; ++p) mbar_arrive_cl(mapa_rank(a_mbC, p));
    }
    mbar_wait_parity_cl(a_mbC, 0u);
    if (wid < BPC) {
        const int b = wid;
        float s = 0.f;
#pragma unroll
        for (int r = 0; r < RANKS; ++r) s += xc[r * 264 + b * 66 + 2 * lane];
        coefA[b * 32 + lane] = entmax_coef(s * invsd, sortb + b * 32, lane);
    }
    __syncthreads();

    for (int t = 0; t < TSTEPS; ++t) {
        const int oldi = t & 1;
        const int ni   = oldi ^ 1;
        const int csl  = (t + 1) & 1;

        // prefetch pre (tid<256: b=tid>>6, d=tid&63)
        float pre_v = 0.f;
        if (tid < 256) {
            pre_v = __ldcs(&g_pre[((size_t)(b0 + (tid >> 6)) * TSTEPS + t) * DIMN
                                  + dbase + (tid & 63)]);
        }

        // ---- phase A: W_h GEMV partials (16 warps, FFMA2) ----
        gemv16(g_WhP, reinterpret_cast<const float4*>(xw + oldi * 2048), part,
               wid, lane, dbase);
        __syncthreads();

        // ---- finish h(t) (tid<256); push h ----
        if (tid < 256) {
            const int b = tid >> 6, d = tid & 63;
            float acc = pre_v;
#pragma unroll
            for (int s = 0; s < 16; ++s) acc += part[s * 256 + b * 64 + d];
            const float* tr = tape + b * NSLOT * 65 + d;
            const float* cf = coefA + b * 32;
#pragma unroll 8
            for (int n = 0; n < NSLOT; ++n) acc += cf[n] * tr[n * 65];
            float h = tanhf(acc);
            __stcs(&out_hseq[((size_t)(b0 + b) * TSTEPS + t) * DIMN + dbase + d], h);
            uint32_t off = a_xw + (unsigned)(ni * 2048 + b * DIMN + dbase + d) * 4u;
#pragma unroll
            for (int p = 0; p < RANKS; ++p) sts_cluster_f32(mapa_rank(off, p), h);
        }
        __syncthreads();
        if (tid == 0) {
#pragma unroll
            for (int p = 0; p < RANKS; ++p) mbar_arrive_cl(mapa_rank(a_mbB, p));
        }
        mbar_wait_parity_cl(a_mbB, (uint32_t)(t & 1));

        // ---- phase B: W_w GEMV partials on full h (FFMA2) ----
        gemv16(g_WwP, reinterpret_cast<const float4*>(xw + ni * 2048), part,
               wid, lane, dbase);
        __syncthreads();

        // ---- phase C (fused): warps 0-3 reduce wvec + full-dot scores + push ----
        if (wid < BPC) {
            const int b = wid;
            float wv0 = 0.f, wv1 = 0.f;
#pragma unroll
            for (int s = 0; s < 16; ++s) {
                wv0 += part[s * 256 + b * 64 + lane];
                wv1 += part[s * 256 + b * 64 + 32 + lane];
            }
            wvec[b * 64 + lane]      = wv0;
            wvec[b * 64 + 32 + lane] = wv1;
            __syncwarp();

            const float* tr = tape + (b * NSLOT + lane) * 65;
            const float* wv = wvec + b * 64;
            const float* hh = xw + ni * 2048 + b * DIMN + dbase;
            float sA = 0.f, sB = 0.f;
#pragma unroll
            for (int d = 0; d < DCH; ++d) {
                float tv = tr[d];
                sA += tv * wv[d];
                sB += tv * hh[d];
            }
            // sC from registers
            float v = wv0 * hh[lane] + wv1 * hh[32 + lane];
#pragma unroll
            for (int o = 16; o > 0; o >>= 1) v += __shfl_xor_sync(0xffffffffu, v, o);

            uint32_t off = a_xc + (unsigned)(csl * 2112 + rk * 264 + b * 66 + 2 * lane) * 4u;
#pragma unroll
            for (int p = 0; p < RANKS; ++p) sts_cluster_f32x2(mapa_rank(off, p), sA, sB);
            if (lane == 0) {
                uint32_t offc = a_xc + (unsigned)(csl * 2112 + rk * 264 + b * 66 + 64) * 4u;
#pragma unroll
                for (int p = 0; p < RANKS; ++p) sts_cluster_f32(mapa_rank(offc, p), v);
            }
        }
        __syncthreads();
        if (tid == 0) {
#pragma unroll
            for (int p = 0; p < RANKS; ++p) mbar_arrive_cl(mapa_rank(a_mbC, p));
        }
        mbar_wait_parity_cl(a_mbC, (uint32_t)csl);

        // ---- phase D1: reduce + beta = entmax(sA) (warps 0-3) ----
        float sBr = 0.f, sCr = 0.f, betar = 0.f;
        if (wid < BPC) {
            const int b = wid;
            const float* base = xc + csl * 2112 + b * 66;
            float sA = 0.f;
#pragma unroll
            for (int r = 0; r < RANKS; ++r) {
                float2 pr = *reinterpret_cast<const float2*>(base + r * 264 + 2 * lane);
                sA  += pr.x;
                sBr += pr.y;
                sCr += base[r * 264 + 64];
            }
            betar = entmax_coef(sA * invsd, sortb + b * 32, lane);
            coefB[b * 32 + lane] = betar;
        }
        __syncthreads();

        // ---- phase D2: alpha(t+1) (warps 0-3) || tape update (warps 4-11) ----
        if (wid < BPC) {
            const int b = wid;
            float rn = ((1.f - betar) * sBr + betar * sCr) * invsd;
            coefA[b * 32 + lane] = entmax_coef(rn, sortb + b * 32, lane);
        } else if (wid < 12) {
            const int idx = wid - 4;
            const int b  = idx >> 1;
            const int n0 = (idx & 1) * 16;
            const float* wv = wvec + b * 64;
            const float* cf = coefB + b * 32 + n0;
            float* tb = tape + (b * NSLOT + n0) * 65;
#pragma unroll
            for (int n = 0; n < 16; ++n) {
                float bt = cf[n], omb = 1.f - bt;
                float* row = tb + n * 65;
                row[lane]      = row[lane]      * omb + bt * wv[lane];
                row[lane + 32] = row[lane + 32] * omb + bt * wv[lane + 32];
            }
        }
        __syncthreads();
    }

    // ---- final outputs ----
    for (int i = tid; i < BPC * NSLOT * DCH; i += NTHR) {
        int b = i >> 11;
        int n = (i >> 6) & 31;
        int d = i & 63;
        out_tape[((size_t)(b0 + b) * NSLOT + n) * DIMN + dbase + d] =
            tape[(b * NSLOT + n) * 65 + d];
    }
    if (tid < 256) {
        const int b = tid >> 6, d = tid & 63;
        // h(2047): ni at t=2047 is 0
        out_hlast[(size_t)(b0 + b) * DIMN + dbase + d] = xw[b * DIMN + dbase + d];
    }
    cluster_sync_();
}

// ---------------- launch ----------------
extern "C" void kernel_launch(void* const* d_in, const int* in_sizes, int n_in,
                              void* d_out, int out_size) {
    const float* x     = (const float*)d_in[0];
    const float* tape0 = (const float*)d_in[1];
    const float* work0 = (const float*)d_in[2];
    const float* Wh    = (const float*)d_in[3];
    const float* Wx    = (const float*)d_in[4];
    const float* bh    = (const float*)d_in[5];
    const float* Ww    = (const float*)d_in[6];

    float* out       = (float*)d_out;
    float* out_hseq  = out;
    float* out_tape  = out + (size_t)BATCH * TSTEPS * DIMN;
    float* out_hlast = out_tape + (size_t)BATCH * NSLOT * DIMN;

    dummy_k<<<1, 32>>>();

    pack_weights<<<(DIMN * DIMN + 511) / 512, 512>>>(Wh, Ww);

    dim3 ggrid(DIMN / 64, (BATCH * TSTEPS) / 128);
    gemm_pre<<<ggrid, 256>>>(x, Wx, bh);

    const int smem_bytes = SM_FLOATS * 4 + 16;
    cudaFuncSetAttribute(recur16, cudaFuncAttributeMaxDynamicSharedMemorySize, smem_bytes);
    recur16<<<(BATCH / BPC) * RANKS, NTHR, smem_bytes>>>(
        tape0, work0, out_hseq, out_tape, out_hlast);
}

// round 17
// speedup vs baseline: 2.8842x; 1.0013x over previous
#include <cuda_runtime.h>
#include <cuda_bf16.h>
#include <cstddef>
#include <cstdint>

#define DIMN   512
#define NSLOT  32
#define BATCH  32
#define TSTEPS 2048
#define RANKS  8      // cluster size = d-chunks
#define BPC    4      // batches per CTA
#define DCH    64     // d columns per CTA
#define NTHR   512

// ---------------- scratch ----------------
__device__ float g_pre[(size_t)BATCH * TSTEPS * DIMN];
__device__ float g_WhP[DIMN * DIMN];   // packed: float4 idx = k4*DIMN + d
__device__ float g_WwP[DIMN * DIMN];

// ---------------- PTX helpers ----------------
__device__ __forceinline__ uint32_t smem_u32(const void* p) {
    uint32_t a;
    asm("{ .reg .u64 t; cvta.to.shared.u64 t, %1; cvt.u32.u64 %0, t; }"
        : "=r"(a) : "l"(p));
    return a;
}
__device__ __forceinline__ uint32_t mapa_rank(uint32_t laddr, uint32_t rank) {
    uint32_t r;
    asm("mapa.shared::cluster.u32 %0, %1, %2;" : "=r"(r) : "r"(laddr), "r"(rank));
    return r;
}
__device__ __forceinline__ void sts_cluster_f32(uint32_t addr, float v) {
    asm volatile("st.shared::cluster.f32 [%0], %1;" :: "r"(addr), "f"(v) : "memory");
}
__device__ __forceinline__ void sts_cluster_f32x2(uint32_t addr, float a, float b) {
    asm volatile("st.shared::cluster.v2.f32 [%0], {%1, %2};"
                 :: "r"(addr), "f"(a), "f"(b) : "memory");
}
__device__ __forceinline__ void mbar_init(uint32_t addr, uint32_t cnt) {
    asm volatile("mbarrier.init.shared.b64 [%0], %1;" :: "r"(addr), "r"(cnt) : "memory");
}
__device__ __forceinline__ void mbar_arrive_cl(uint32_t remAddr) {
    asm volatile("mbarrier.arrive.release.cluster.shared::cluster.b64 _, [%0];"
                 :: "r"(remAddr) : "memory");
}
__device__ __forceinline__ void mbar_wait_parity_cl(uint32_t addr, uint32_t parity) {
    asm volatile(
        "{\n\t"
        ".reg .pred P;\n\t"
        "LAB_WAIT_%=:\n\t"
        "mbarrier.try_wait.parity.acquire.cluster.shared::cta.b64 P, [%0], %1, 0x989680;\n\t"
        "@P bra.uni LAB_DONE_%=;\n\t"
        "bra.uni LAB_WAIT_%=;\n\t"
        "LAB_DONE_%=:\n\t"
        "}"
        :: "r"(addr), "r"(parity) : "memory");
}
__device__ __forceinline__ void cluster_sync_() {
    asm volatile("barrier.cluster.arrive.aligned;\n\tbarrier.cluster.wait.aligned;" ::: "memory");
}

// ---- packed f32x2 FMA (FFMA2) ----
__device__ __forceinline__ void fma2(unsigned long long& acc,
                                     unsigned long long a, unsigned long long b) {
    asm("fma.rn.f32x2 %0, %1, %2, %0;" : "+l"(acc) : "l"(a), "l"(b));
}
__device__ __forceinline__ unsigned long long f4lo(const float4& v) {
    return reinterpret_cast<const unsigned long long*>(&v)[0];
}
__device__ __forceinline__ unsigned long long f4hi(const float4& v) {
    return reinterpret_cast<const unsigned long long*>(&v)[1];
}
__device__ __forceinline__ float hadd2(unsigned long long v) {
    float2 f;
    asm("mov.b64 {%0, %1}, %2;" : "=f"(f.x), "=f"(f.y) : "l"(v));
    return f.x + f.y;
}

__global__ void dummy_k() {}

// ---------------- weight packing ----------------
__global__ void pack_weights(const float* __restrict__ Wh,
                             const float* __restrict__ Ww) {
    int idx = blockIdx.x * blockDim.x + threadIdx.x;
    if (idx >= DIMN * DIMN) return;
    int d = idx / DIMN;
    int k = idx % DIMN;
    int dst = ((k >> 2) * DIMN + d) * 4 + (k & 3);
    g_WhP[dst] = Wh[idx];
    g_WwP[dst] = Ww[idx];
}

// ---------------- pre-GEMM ----------------
__global__ __launch_bounds__(256) void gemm_pre(
    const float* __restrict__ X,
    const float* __restrict__ W,
    const float* __restrict__ bias)
{
    __shared__ float As[8][128];
    __shared__ float Bs[8][64];
    const int tid = threadIdx.x;
    const int m0 = blockIdx.y * 128;
    const int n0 = blockIdx.x * 64;
    const int trow = tid >> 4;
    const int tcol = tid & 15;
    float acc[8][4];
#pragma unroll
    for (int i = 0; i < 8; ++i)
#pragma unroll
        for (int j = 0; j < 4; ++j) acc[i][j] = 0.f;
    const int a_m  = tid >> 1;
    const int a_k4 = (tid & 1) * 4;
    for (int k0 = 0; k0 < DIMN; k0 += 8) {
        float4 av = *reinterpret_cast<const float4*>(
            X + (size_t)(m0 + a_m) * DIMN + k0 + a_k4);
        As[a_k4 + 0][a_m] = av.x;
        As[a_k4 + 1][a_m] = av.y;
        As[a_k4 + 2][a_m] = av.z;
        As[a_k4 + 3][a_m] = av.w;
        if (tid < 128) {
            int bn  = tid >> 1;
            int bk4 = (tid & 1) * 4;
            float4 bv = *reinterpret_cast<const float4*>(
                W + (size_t)(n0 + bn) * DIMN + k0 + bk4);
            Bs[bk4 + 0][bn] = bv.x;
            Bs[bk4 + 1][bn] = bv.y;
            Bs[bk4 + 2][bn] = bv.z;
            Bs[bk4 + 3][bn] = bv.w;
        }
        __syncthreads();
#pragma unroll
        for (int kk = 0; kk < 8; ++kk) {
            float4 ra0 = *reinterpret_cast<const float4*>(&As[kk][trow * 8]);
            float4 ra1 = *reinterpret_cast<const float4*>(&As[kk][trow * 8 + 4]);
            float4 rb  = *reinterpret_cast<const float4*>(&Bs[kk][tcol * 4]);
            float ra[8] = {ra0.x, ra0.y, ra0.z, ra0.w, ra1.x, ra1.y, ra1.z, ra1.w};
            float rbv[4] = {rb.x, rb.y, rb.z, rb.w};
#pragma unroll
            for (int i = 0; i < 8; ++i)
#pragma unroll
                for (int j = 0; j < 4; ++j) acc[i][j] += ra[i] * rbv[j];
        }
        __syncthreads();
    }
    float4 bj = *reinterpret_cast<const float4*>(bias + n0 + tcol * 4);
#pragma unroll
    for (int i = 0; i < 8; ++i) {
        float4 v;
        v.x = acc[i][0] + bj.x;
        v.y = acc[i][1] + bj.y;
        v.z = acc[i][2] + bj.z;
        v.w = acc[i][3] + bj.w;
        *reinterpret_cast<float4*>(
            &g_pre[(size_t)(m0 + trow * 8 + i) * DIMN + n0 + tcol * 4]) = v;
    }
}

// ---------------- exact entmax-1.5 (warp-collective, lane = slot) ----------------
__device__ __forceinline__ float entmax_coef(float raw, float* __restrict__ sb, int lane) {
    const unsigned FULL = 0xffffffffu;
    float z = raw * 0.5f;
    float m = z;
#pragma unroll
    for (int o = 16; o > 0; o >>= 1) m = fmaxf(m, __shfl_xor_sync(FULL, m, o));
    z -= m;
    int rank = 0;
#pragma unroll
    for (int j = 0; j < 32; ++j) {
        float zj = __shfl_sync(FULL, z, j);
        rank += (zj > z) || (zj == z && j < lane);
    }
    sb[rank] = z;
    __syncwarp();
    float zs = sb[lane];
    float cs = zs, cq = zs * zs;
#pragma unroll
    for (int o = 1; o < 32; o <<= 1) {
        float a  = __shfl_up_sync(FULL, cs, o);
        float bq = __shfl_up_sync(FULL, cq, o);
        if (lane >= o) { cs += a; cq += bq; }
    }
    float k    = (float)(lane + 1);
    float mean = cs / k;
    float msq  = cq / k;
    float ss   = k * (msq - mean * mean);
    float delta = fmaxf((1.f - ss) / k, 0.f);
    float tau   = mean - sqrtf(delta);
    unsigned sup = __ballot_sync(FULL, tau <= zs);
    int kstar = __popc(sup) - 1;
    float tau_star = __shfl_sync(FULL, tau, kstar);
    float p = fmaxf(z - tau_star, 0.f);
    return p * p;
}

// ---------------- GEMV partials via FFMA2: 16 warps = 16 k-segments of 32 ------
__device__ __forceinline__ void gemv16(const float* __restrict__ Wp,
                                       const float4* __restrict__ xw4, // [4][128]
                                       float* __restrict__ part,
                                       int wid, int lane, int dbase) {
    const float4* W4 = reinterpret_cast<const float4*>(Wp)
                       + (size_t)(wid * 8) * DIMN + dbase + lane;
    unsigned long long a0 = 0ull, a1 = 0ull, a2 = 0ull, a3 = 0ull;
    unsigned long long b0 = 0ull, b1 = 0ull, b2 = 0ull, b3 = 0ull;
#pragma unroll
    for (int i = 0; i < 8; ++i) {
        float4 w0 = W4[(size_t)i * DIMN];
        float4 w1 = W4[(size_t)i * DIMN + 32];
        float4 k0 = xw4[0 * 128 + wid * 8 + i];
        float4 k1 = xw4[1 * 128 + wid * 8 + i];
        float4 k2 = xw4[2 * 128 + wid * 8 + i];
        float4 k3 = xw4[3 * 128 + wid * 8 + i];
        unsigned long long w0l = f4lo(w0), w0h = f4hi(w0);
        unsigned long long w1l = f4lo(w1), w1h = f4hi(w1);
        fma2(a0, w0l, f4lo(k0));  fma2(a0, w0h, f4hi(k0));
        fma2(a1, w0l, f4lo(k1));  fma2(a1, w0h, f4hi(k1));
        fma2(a2, w0l, f4lo(k2));  fma2(a2, w0h, f4hi(k2));
        fma2(a3, w0l, f4lo(k3));  fma2(a3, w0h, f4hi(k3));
        fma2(b0, w1l, f4lo(k0));  fma2(b0, w1h, f4hi(k0));
        fma2(b1, w1l, f4lo(k1));  fma2(b1, w1h, f4hi(k1));
        fma2(b2, w1l, f4lo(k2));  fma2(b2, w1h, f4hi(k2));
        fma2(b3, w1l, f4lo(k3));  fma2(b3, w1h, f4hi(k3));
    }
    float* pp = part + wid * 256 + lane;
    pp[0]   = hadd2(a0);  pp[64]  = hadd2(a1);
    pp[128] = hadd2(a2);  pp[192] = hadd2(a3);
    pp[32]  = hadd2(b0);  pp[96]  = hadd2(b1);
    pp[160] = hadd2(b2);  pp[224] = hadd2(b3);
}

// ---------------- SMEM float offsets ----------------
#define SM_PART   0       // [16][4][64]          4096
#define SM_XW     4096    // [2][4][512]          4096
#define SM_WVEC   8192    // [4][64]              256
#define SM_COEFA  8448    // [4][32]              128
#define SM_COEFB  8576    // [4][32]              128
#define SM_SORT   8704    // [4][32]              128
#define SM_TAPE   8832    // [4][32][65]          8320
#define SM_XC     17152   // [2][8][4][66]        4224
#define SM_SCRA   21376   // [8][32]              256
#define SM_SCRB   21632   // [8][32]              256
#define SM_SCRC   21888   // [8]                  8
#define SM_MBARB  21896   // u64
#define SM_MBARC  21898   // u64
#define SM_FLOATS 21900

// ---------------- persistent recurrence ----------------
__global__ void __launch_bounds__(NTHR, 1) __cluster_dims__(RANKS, 1, 1)
recur17(const float* __restrict__ tape0,
        const float* __restrict__ work0,
        float* __restrict__ out_hseq,
        float* __restrict__ out_tape,
        float* __restrict__ out_hlast)
{
    extern __shared__ float sm[];
    float* part  = sm + SM_PART;
    float* xw    = sm + SM_XW;
    float* wvec  = sm + SM_WVEC;
    float* coefA = sm + SM_COEFA;
    float* coefB = sm + SM_COEFB;
    float* sortb = sm + SM_SORT;
    float* tape  = sm + SM_TAPE;
    float* xc    = sm + SM_XC;
    float* scrA  = sm + SM_SCRA;
    float* scrB  = sm + SM_SCRB;
    float* scrC  = sm + SM_SCRC;

    const int tid  = threadIdx.x;
    const int lane = tid & 31;
    const int wid  = tid >> 5;
    const int rk   = blockIdx.x & (RANKS - 1);
    const int bg   = blockIdx.x >> 3;
    const int b0   = bg * BPC;
    const int dbase = rk * DCH;
    const float invsd = 0.044194173824159216f;  // 1/sqrt(512)

    const uint32_t sbase = smem_u32(sm);
    const uint32_t a_xw  = sbase + SM_XW * 4u;
    const uint32_t a_xc  = sbase + SM_XC * 4u;
    const uint32_t a_mbB = sbase + SM_MBARB * 4u;
    const uint32_t a_mbC = sbase + SM_MBARC * 4u;

    if (tid == 0) {
        mbar_init(a_mbB, RANKS);
        mbar_init(a_mbC, RANKS);
    }

    // ---- prologue loads ----
    for (int i = tid; i < BPC * NSLOT * DCH; i += NTHR) {
        int b = i >> 11;
        int n = (i >> 6) & 31;
        int d = i & 63;
        tape[(b * NSLOT + n) * 65 + d] =
            tape0[((size_t)(b0 + b) * NSLOT + n) * DIMN + dbase + d];
    }
    for (int i = tid; i < BPC * DIMN; i += NTHR) {
        int b = i >> 9;
        int k = i & 511;
        xw[b * DIMN + k] = work0[(size_t)(b0 + b) * DIMN + k];
    }
    __syncthreads();
    cluster_sync_();

    // ---- initial read-scores exchange (parity 0): warps 0-3 full 64-d dots ----
    if (wid < BPC) {
        const int b = wid;
        const float* tr = tape + (b * NSLOT + lane) * 65;
        const float* wk = xw + b * DIMN + dbase;
        float s = 0.f;
#pragma unroll
        for (int d = 0; d < DCH; ++d) s += tr[d] * wk[d];
        uint32_t off = a_xc + (unsigned)(rk * 264 + b * 66 + 2 * lane) * 4u;
#pragma unroll
        for (int p = 0; p < RANKS; ++p) sts_cluster_f32(mapa_rank(off, p), s);
    }
    __syncthreads();
    if (tid == 0) {
#pragma unroll
        for (int p = 0; p < RANKS; ++p) mbar_arrive_cl(mapa_rank(a_mbC, p));
    }
    mbar_wait_parity_cl(a_mbC, 0u);
    if (wid < BPC) {
        const int b = wid;
        float s = 0.f;
#pragma unroll
        for (int r = 0; r < RANKS; ++r) s += xc[r * 264 + b * 66 + 2 * lane];
        coefA[b * 32 + lane] = entmax_coef(s * invsd, sortb + b * 32, lane);
    }
    __syncthreads();

    for (int t = 0; t < TSTEPS; ++t) {
        const int oldi = t & 1;
        const int ni   = oldi ^ 1;
        const int csl  = (t + 1) & 1;

        // prefetch pre (tid<256: b=tid>>6, d=tid&63)
        float pre_v = 0.f;
        if (tid < 256) {
            pre_v = __ldcs(&g_pre[((size_t)(b0 + (tid >> 6)) * TSTEPS + t) * DIMN
                                  + dbase + (tid & 63)]);
        }

        // ---- phase A: W_h GEMV partials (16 warps, FFMA2) ----
        gemv16(g_WhP, reinterpret_cast<const float4*>(xw + oldi * 2048), part,
               wid, lane, dbase);
        __syncthreads();

        // ---- finish h(t) (tid<256); push h ----
        if (tid < 256) {
            const int b = tid >> 6, d = tid & 63;
            float acc = pre_v;
#pragma unroll
            for (int s = 0; s < 16; ++s) acc += part[s * 256 + b * 64 + d];
            const float* tr = tape + b * NSLOT * 65 + d;
            const float* cf = coefA + b * 32;
#pragma unroll 8
            for (int n = 0; n < NSLOT; ++n) acc += cf[n] * tr[n * 65];
            float h = tanhf(acc);
            __stcs(&out_hseq[((size_t)(b0 + b) * TSTEPS + t) * DIMN + dbase + d], h);
            uint32_t off = a_xw + (unsigned)(ni * 2048 + b * DIMN + dbase + d) * 4u;
#pragma unroll
            for (int p = 0; p < RANKS; ++p) sts_cluster_f32(mapa_rank(off, p), h);
        }
        __syncthreads();
        if (tid == 0) {
#pragma unroll
            for (int p = 0; p < RANKS; ++p) mbar_arrive_cl(mapa_rank(a_mbB, p));
        }
        mbar_wait_parity_cl(a_mbB, (uint32_t)(t & 1));

        // ---- phase B: W_w GEMV partials on full h (FFMA2) ----
        gemv16(g_WwP, reinterpret_cast<const float4*>(xw + ni * 2048), part,
               wid, lane, dbase);
        __syncthreads();

        // ---- phase C1 (split): warps 0-7 half wvec reduce + half dots -> scratch ----
        if (wid < 8) {
            const int b = wid & 3, half = wid >> 2;
            const int dh = half * 32;
            float wv = 0.f;
#pragma unroll
            for (int s = 0; s < 16; ++s) wv += part[s * 256 + b * 64 + dh + lane];
            wvec[b * 64 + dh + lane] = wv;
            __syncwarp();

            const float* tr  = tape + (b * NSLOT + lane) * 65 + dh;
            const float* wvp = wvec + b * 64 + dh;
            const float* hh  = xw + ni * 2048 + b * DIMN + dbase + dh;
            float sA = 0.f, sB = 0.f;
#pragma unroll
            for (int d = 0; d < 32; ++d) {
                float tv = tr[d];
                sA += tv * wvp[d];
                sB += tv * hh[d];
            }
            float v = wv * hh[lane];
#pragma unroll
            for (int o = 16; o > 0; o >>= 1) v += __shfl_xor_sync(0xffffffffu, v, o);

            const int g = half * 4 + b;
            scrA[g * 32 + lane] = sA;
            scrB[g * 32 + lane] = sB;
            if (lane == 0) scrC[g] = v;
        }
        __syncthreads();

        // ---- phase C2: warps 0-3 combine halves + push ----
        if (wid < BPC) {
            const int b = wid;
            float sA = scrA[b * 32 + lane] + scrA[(4 + b) * 32 + lane];
            float sB = scrB[b * 32 + lane] + scrB[(4 + b) * 32 + lane];
            uint32_t off = a_xc + (unsigned)(csl * 2112 + rk * 264 + b * 66 + 2 * lane) * 4u;
#pragma unroll
            for (int p = 0; p < RANKS; ++p) sts_cluster_f32x2(mapa_rank(off, p), sA, sB);
            if (lane == 0) {
                float v = scrC[b] + scrC[4 + b];
                uint32_t offc = a_xc + (unsigned)(csl * 2112 + rk * 264 + b * 66 + 64) * 4u;
#pragma unroll
                for (int p = 0; p < RANKS; ++p) sts_cluster_f32(mapa_rank(offc, p), v);
            }
        }
        __syncthreads();
        if (tid == 0) {
#pragma unroll
            for (int p = 0; p < RANKS; ++p) mbar_arrive_cl(mapa_rank(a_mbC, p));
        }
        mbar_wait_parity_cl(a_mbC, (uint32_t)csl);

        // ---- phase D1: reduce + beta = entmax(sA) (warps 0-3) ----
        float sBr = 0.f, sCr = 0.f, betar = 0.f;
        if (wid < BPC) {
            const int b = wid;
            const float* base = xc + csl * 2112 + b * 66;
            float sA = 0.f;
#pragma unroll
            for (int r = 0; r < RANKS; ++r) {
                float2 pr = *reinterpret_cast<const float2*>(base + r * 264 + 2 * lane);
                sA  += pr.x;
                sBr += pr.y;
                sCr += base[r * 264 + 64];
            }
            betar = entmax_coef(sA * invsd, sortb + b * 32, lane);
            coefB[b * 32 + lane] = betar;
        }
        __syncthreads();

        // ---- phase D2: alpha(t+1) (warps 0-3) || tape update (warps 4-11) ----
        if (wid < BPC) {
            const int b = wid;
            float rn = ((1.f - betar) * sBr + betar * sCr) * invsd;
            coefA[b * 32 + lane] = entmax_coef(rn, sortb + b * 32, lane);
        } else if (wid < 12) {
            const int idx = wid - 4;
            const int b  = idx >> 1;
            const int n0 = (idx & 1) * 16;
            const float* wv = wvec + b * 64;
            const float* cf = coefB + b * 32 + n0;
            float* tb = tape + (b * NSLOT + n0) * 65;
#pragma unroll
            for (int n = 0; n < 16; ++n) {
                float bt = cf[n], omb = 1.f - bt;
                float* row = tb + n * 65;
                row[lane]      = row[lane]      * omb + bt * wv[lane];
                row[lane + 32] = row[lane + 32] * omb + bt * wv[lane + 32];
            }
        }
        __syncthreads();
    }

    // ---- final outputs ----
    for (int i = tid; i < BPC * NSLOT * DCH; i += NTHR) {
        int b = i >> 11;
        int n = (i >> 6) & 31;
        int d = i & 63;
        out_tape[((size_t)(b0 + b) * NSLOT + n) * DIMN + dbase + d] =
            tape[(b * NSLOT + n) * 65 + d];
    }
    if (tid < 256) {
        const int b = tid >> 6, d = tid & 63;
        // h(2047): ni at t=2047 is 0
        out_hlast[(size_t)(b0 + b) * DIMN + dbase + d] = xw[b * DIMN + dbase + d];
    }
    cluster_sync_();
}

// ---------------- launch ----------------
extern "C" void kernel_launch(void* const* d_in, const int* in_sizes, int n_in,
                              void* d_out, int out_size) {
    const float* x     = (const float*)d_in[0];
    const float* tape0 = (const float*)d_in[1];
    const float* work0 = (const float*)d_in[2];
    const float* Wh    = (const float*)d_in[3];
    const float* Wx    = (const float*)d_in[4];
    const float* bh    = (const float*)d_in[5];
    const float* Ww    = (const float*)d_in[6];

    float* out       = (float*)d_out;
    float* out_hseq  = out;
    float* out_tape  = out + (size_t)BATCH * TSTEPS * DIMN;
    float* out_hlast = out_tape + (size_t)BATCH * NSLOT * DIMN;

    dummy_k<<<1, 32>>>();

    pack_weights<<<(DIMN * DIMN + 511) / 512, 512>>>(Wh, Ww);

    dim3 ggrid(DIMN / 64, (BATCH * TSTEPS) / 128);
    gemm_pre<<<ggrid, 256>>>(x, Wx, bh);

    const int smem_bytes = SM_FLOATS * 4 + 16;
    cudaFuncSetAttribute(recur17, cudaFuncAttributeMaxDynamicSharedMemorySize, smem_bytes);
    recur17<<<(BATCH / BPC) * RANKS, NTHR, smem_bytes>>>(
        tape0, work0, out_hseq, out_tape, out_hlast);
}